// round 5
// baseline (speedup 1.0000x reference)
#include <cuda_runtime.h>
#include <cuda_bf16.h>
#include <math.h>

// ---------------------------------------------------------------------------
// Problem constants (DeepseekV3 MLA prefill, B=1, S=2048)
// ---------------------------------------------------------------------------
#define S_LEN  2048
#define HID    2048
#define NH     16
#define NOPE   128
#define ROPE_D 64
#define QHD    192     // NOPE + ROPE
#define VD     128
#define QLR    1536
#define KVLR   512
#define CKVD   576     // KVLR + ROPE

// ---------------------------------------------------------------------------
// Scratch (static __device__ arrays — no runtime allocation)
// ---------------------------------------------------------------------------
__device__ float g_qa  [S_LEN * QLR];          // hidden @ Wqa (normed in place)
__device__ float g_q   [S_LEN * NH * QHD];     // q_a @ Wqb, RoPE applied in place
__device__ float g_ckv [S_LEN * CKVD];         // hidden @ Wkva (raw)
__device__ float g_ckvn[S_LEN * KVLR];         // rmsnorm(c_kv)
__device__ float g_kpe [S_LEN * ROPE_D];       // roped shared k_pe
__device__ float g_kv  [S_LEN * NH * (NOPE + VD)]; // ckvn @ Wkvb: per head [k_nope|v]
__device__ float g_attn[S_LEN * NH * VD];      // attention output (s, h*128+d)

// ---------------------------------------------------------------------------
// Generic tiled GEMM: C[M,N] = A[M,K] @ B[K,N], row-major, fp32.
// 128x128 block, 16 k-step, 256 threads, 8x8 register microtile.
// Requires: M % 128 == 0, K % 16 == 0. N is guarded.
// ---------------------------------------------------------------------------
__global__ void __launch_bounds__(256) gemm_kernel(
    float* __restrict__ C, const float* __restrict__ A, const float* __restrict__ B,
    int M, int N, int K, int lda, int ldb, int ldc)
{
    __shared__ float As[16][128];
    __shared__ float Bs[16][128];

    const int tid = threadIdx.x;
    const int tx  = tid & 15;
    const int ty  = tid >> 4;
    const int m0  = blockIdx.y * 128;
    const int n0  = blockIdx.x * 128;

    float c[8][8];
#pragma unroll
    for (int i = 0; i < 8; i++)
#pragma unroll
        for (int j = 0; j < 8; j++) c[i][j] = 0.f;

    for (int k0 = 0; k0 < K; k0 += 16) {
        // Load A tile (128 rows x 16 k) transposed into As[k][m]
#pragma unroll
        for (int t = 0; t < 2; t++) {
            int v  = tid * 2 + t;           // 0..511
            int m  = v >> 2;
            int kq = v & 3;
            float4 a = *(const float4*)(A + (size_t)(m0 + m) * lda + k0 + kq * 4);
            As[kq * 4 + 0][m] = a.x;
            As[kq * 4 + 1][m] = a.y;
            As[kq * 4 + 2][m] = a.z;
            As[kq * 4 + 3][m] = a.w;
        }
        // Load B tile (16 k x 128 n)
#pragma unroll
        for (int t = 0; t < 2; t++) {
            int v  = tid + t * 256;         // 0..511
            int k  = v >> 5;
            int nq = v & 31;
            int n  = n0 + nq * 4;
            float4 b;
            if (n + 3 < N) {
                b = *(const float4*)(B + (size_t)(k0 + k) * ldb + n);
            } else {
                const float* bp = B + (size_t)(k0 + k) * ldb;
                b.x = (n + 0 < N) ? bp[n + 0] : 0.f;
                b.y = (n + 1 < N) ? bp[n + 1] : 0.f;
                b.z = (n + 2 < N) ? bp[n + 2] : 0.f;
                b.w = (n + 3 < N) ? bp[n + 3] : 0.f;
            }
            *(float4*)&Bs[k][nq * 4] = b;
        }
        __syncthreads();

#pragma unroll
        for (int k = 0; k < 16; k++) {
            float4 a0 = *(float4*)&As[k][ty * 8];
            float4 a1 = *(float4*)&As[k][ty * 8 + 4];
            float4 b0 = *(float4*)&Bs[k][tx * 8];
            float4 b1 = *(float4*)&Bs[k][tx * 8 + 4];
            float av[8] = {a0.x, a0.y, a0.z, a0.w, a1.x, a1.y, a1.z, a1.w};
            float bv[8] = {b0.x, b0.y, b0.z, b0.w, b1.x, b1.y, b1.z, b1.w};
#pragma unroll
            for (int i = 0; i < 8; i++)
#pragma unroll
                for (int j = 0; j < 8; j++) c[i][j] += av[i] * bv[j];
        }
        __syncthreads();
    }

#pragma unroll
    for (int i = 0; i < 8; i++) {
        int m = m0 + ty * 8 + i;
#pragma unroll
        for (int j = 0; j < 8; j++) {
            int n = n0 + tx * 8 + j;
            if (n < N) C[(size_t)m * ldc + n] = c[i][j];
        }
    }
}

// ---------------------------------------------------------------------------
// RMSNorm: one block per row. out[i] = w[i] * x[i] * rsqrt(mean(x^2) + eps)
// ---------------------------------------------------------------------------
__global__ void __launch_bounds__(256) rmsnorm_kernel(
    float* __restrict__ out, const float* __restrict__ in,
    const float* __restrict__ w, int D, int ldin, int ldout)
{
    const int row = blockIdx.x;
    const float* x = in + (size_t)row * ldin;
    float* y = out + (size_t)row * ldout;

    float s = 0.f;
    for (int i = threadIdx.x; i < D; i += 256) {
        float v = x[i];
        s += v * v;
    }
#pragma unroll
    for (int o = 16; o; o >>= 1) s += __shfl_xor_sync(0xffffffffu, s, o);

    __shared__ float red[8];
    __shared__ float inv_s;
    if ((threadIdx.x & 31) == 0) red[threadIdx.x >> 5] = s;
    __syncthreads();
    if (threadIdx.x == 0) {
        float t = 0.f;
#pragma unroll
        for (int i = 0; i < 8; i++) t += red[i];
        inv_s = rsqrtf(t / (float)D + 1e-6f);
    }
    __syncthreads();
    float inv = inv_s;
    for (int i = threadIdx.x; i < D; i += 256) y[i] = w[i] * (x[i] * inv);
}

// ---------------------------------------------------------------------------
// RoPE (deinterleave + rotate_half fused):
//   y[j] = x[2j], y[j+32] = x[2j+1];  cos/sin period 32
//   out[j]    = x[2j]  *c - x[2j+1]*s
//   out[j+32] = x[2j+1]*c + x[2j]  *s
// q_pe updated in place (16 heads, cols [128,192) of each 192-wide head slot),
// k_pe read from raw ckv tail, written to g_kpe.
// Block = one token, 544 threads = 16 head-warps + 1 kpe warp.
// ---------------------------------------------------------------------------
__global__ void rope_kernel(float* __restrict__ q, float* __restrict__ kpe,
                            const float* __restrict__ ckv,
                            const int* __restrict__ pos_ids)
{
    const int srow = blockIdx.x;
    const int tid  = threadIdx.x;
    const int j    = tid & 31;

    const float pos  = (float)pos_ids[srow];
    const float freq = __expf(-((2.f * (float)j) / 64.f) * logf(10000.f));
    const float ang  = pos * freq;
    float cv, sv;
    __sincosf(ang, &sv, &cv);

    if (tid < NH * 32) {
        const int h = tid >> 5;
        float* base = q + (size_t)srow * (NH * QHD) + h * QHD + NOPE;
        float x0 = base[2 * j];
        float x1 = base[2 * j + 1];
        __syncwarp();
        base[j]      = x0 * cv - x1 * sv;
        base[32 + j] = x1 * cv + x0 * sv;
    } else {
        const float* src = ckv + (size_t)srow * CKVD + KVLR;
        float x0 = src[2 * j];
        float x1 = src[2 * j + 1];
        float* dst = kpe + (size_t)srow * ROPE_D;
        dst[j]      = x0 * cv - x1 * sv;
        dst[32 + j] = x1 * cv + x0 * sv;
    }
}

// ---------------------------------------------------------------------------
// Causal flash attention, fp32.
//   BM=BN=64, D=192 (nope128 + rope64), DV=128, 256 threads.
//   Thread (ty,tx), ty=tid/16, tx=tid%16:
//     scores: 4 q-rows (ty*4..) x 4 k-cols (tx*4..)
//     PV/acc: same 4 q-rows x 8 v-dims (tx*8..)
//   Row softmax state reduced across the 16 tx threads via shfl (width 16).
// ---------------------------------------------------------------------------
#define FA_BM 64
#define FA_BN 64
#define FA_D  192
#define FA_DP 196   // padded row for sQ/sK
#define FA_DV 128
#define FA_SMEM_FLOATS (FA_BM*FA_DP + FA_BN*FA_DP + FA_BN*FA_DV + FA_BM*FA_BN)

__global__ void __launch_bounds__(256) flash_kernel(
    float* __restrict__ O, const float* __restrict__ Q,
    const float* __restrict__ KV, const float* __restrict__ KPE)
{
    extern __shared__ float sm[];
    float* sQ = sm;                           // 64 x 196
    float* sK = sQ + FA_BM * FA_DP;           // 64 x 196
    float* sV = sK + FA_BN * FA_DP;           // 64 x 128
    float* sP = sV + FA_BN * FA_DV;           // 64 x 64

    const int tid = threadIdx.x;
    const int tx  = tid & 15;
    const int ty  = tid >> 4;
    const int h   = blockIdx.y;
    const int qb  = blockIdx.x;
    const int q0  = qb * FA_BM;

    // Load Q tile (64 x 192) as float4
    for (int v = tid; v < FA_BM * 48; v += 256) {
        int r = v / 48, cc = v % 48;
        float4 val = *(const float4*)(Q + (size_t)(q0 + r) * (NH * QHD) + h * QHD + cc * 4);
        *(float4*)(sQ + r * FA_DP + cc * 4) = val;
    }

    float acc[4][8];
    float m_i[4], l_i[4];
#pragma unroll
    for (int i = 0; i < 4; i++) {
        m_i[i] = -1e30f;
        l_i[i] = 0.f;
#pragma unroll
        for (int j = 0; j < 8; j++) acc[i][j] = 0.f;
    }
    const float scale = rsqrtf((float)QHD);

    for (int kb = 0; kb <= qb; kb++) {
        const int k0 = kb * FA_BN;
        __syncthreads();   // previous PV done with sV/sP
        // Load K tile: cols [0,128) = k_nope, [128,192) = shared roped k_pe
        for (int v = tid; v < FA_BN * 48; v += 256) {
            int r = v / 48, cc = v % 48;
            float4 val;
            if (cc < 32)
                val = *(const float4*)(KV + (size_t)(k0 + r) * (NH * 256) + h * 256 + cc * 4);
            else
                val = *(const float4*)(KPE + (size_t)(k0 + r) * ROPE_D + (cc - 32) * 4);
            *(float4*)(sK + r * FA_DP + cc * 4) = val;
        }
        // Load V tile (64 x 128)
        for (int v = tid; v < FA_BN * 32; v += 256) {
            int r = v / 32, cc = v % 32;
            float4 val = *(const float4*)(KV + (size_t)(k0 + r) * (NH * 256) + h * 256 + NOPE + cc * 4);
            *(float4*)(sV + r * FA_DV + cc * 4) = val;
        }
        __syncthreads();

        // Scores: 4x4 microtile
        float s4[4][4];
#pragma unroll
        for (int i = 0; i < 4; i++)
#pragma unroll
            for (int j = 0; j < 4; j++) s4[i][j] = 0.f;

#pragma unroll 4
        for (int d = 0; d < FA_D; d += 4) {
            float4 qv[4], kv4[4];
#pragma unroll
            for (int i = 0; i < 4; i++) qv[i]  = *(float4*)(sQ + (ty * 4 + i) * FA_DP + d);
#pragma unroll
            for (int j = 0; j < 4; j++) kv4[j] = *(float4*)(sK + (tx * 4 + j) * FA_DP + d);
#pragma unroll
            for (int i = 0; i < 4; i++)
#pragma unroll
                for (int j = 0; j < 4; j++)
                    s4[i][j] += qv[i].x * kv4[j].x + qv[i].y * kv4[j].y
                              + qv[i].z * kv4[j].z + qv[i].w * kv4[j].w;
        }

        // Scale + causal mask + online softmax
#pragma unroll
        for (int i = 0; i < 4; i++) {
            const int qi = q0 + ty * 4 + i;
            float rmax = -1e30f;
#pragma unroll
            for (int j = 0; j < 4; j++) {
                int kj = k0 + tx * 4 + j;
                float v = (kj <= qi) ? s4[i][j] * scale : -1e30f;
                s4[i][j] = v;
                rmax = fmaxf(rmax, v);
            }
#pragma unroll
            for (int o = 8; o; o >>= 1)
                rmax = fmaxf(rmax, __shfl_xor_sync(0xffffffffu, rmax, o, 16));

            float m_new = fmaxf(m_i[i], rmax);
            float alpha = __expf(m_i[i] - m_new);
            float rsum = 0.f;
#pragma unroll
            for (int j = 0; j < 4; j++) {
                float p = __expf(s4[i][j] - m_new);
                s4[i][j] = p;
                rsum += p;
            }
#pragma unroll
            for (int o = 8; o; o >>= 1)
                rsum += __shfl_xor_sync(0xffffffffu, rsum, o, 16);

            l_i[i] = l_i[i] * alpha + rsum;
            m_i[i] = m_new;
#pragma unroll
            for (int j = 0; j < 8; j++) acc[i][j] *= alpha;
#pragma unroll
            for (int j = 0; j < 4; j++)
                sP[(ty * 4 + i) * FA_BN + tx * 4 + j] = s4[i][j];
        }
        __syncthreads();

        // PV: acc[4][8] += sP[4 rows][64] @ sV[64][8 dims]
#pragma unroll 4
        for (int kc = 0; kc < FA_BN; kc++) {
            float4 v0 = *(float4*)(sV + kc * FA_DV + tx * 8);
            float4 v1 = *(float4*)(sV + kc * FA_DV + tx * 8 + 4);
#pragma unroll
            for (int i = 0; i < 4; i++) {
                float p = sP[(ty * 4 + i) * FA_BN + kc];
                acc[i][0] += p * v0.x; acc[i][1] += p * v0.y;
                acc[i][2] += p * v0.z; acc[i][3] += p * v0.w;
                acc[i][4] += p * v1.x; acc[i][5] += p * v1.y;
                acc[i][6] += p * v1.z; acc[i][7] += p * v1.w;
            }
        }
    }

    // Epilogue: O[(q0+qr), h*128 + tx*8 + j] = acc / l
#pragma unroll
    for (int i = 0; i < 4; i++) {
        float inv_l = 1.f / l_i[i];
        float* op = O + (size_t)(q0 + ty * 4 + i) * (NH * VD) + h * VD + tx * 8;
#pragma unroll
        for (int j = 0; j < 8; j++) op[j] = acc[i][j] * inv_l;
    }
}

// ---------------------------------------------------------------------------
// Launch
// ---------------------------------------------------------------------------
extern "C" void kernel_launch(void* const* d_in, const int* in_sizes, int n_in,
                              void* d_out, int out_size)
{
    const float* hidden = (const float*)d_in[0];
    const int*   pos    = (const int*)d_in[1];
    const float* Wqa    = (const float*)d_in[2];
    const float* qa_ln  = (const float*)d_in[3];
    const float* Wqb    = (const float*)d_in[4];
    const float* Wkva   = (const float*)d_in[5];
    const float* kv_ln  = (const float*)d_in[6];
    const float* Wkvb   = (const float*)d_in[7];
    const float* Wo     = (const float*)d_in[8];
    float* out = (float*)d_out;

    float *qa, *q, *ckv, *ckvn, *kpe, *kv, *attn;
    cudaGetSymbolAddress((void**)&qa,   g_qa);
    cudaGetSymbolAddress((void**)&q,    g_q);
    cudaGetSymbolAddress((void**)&ckv,  g_ckv);
    cudaGetSymbolAddress((void**)&ckvn, g_ckvn);
    cudaGetSymbolAddress((void**)&kpe,  g_kpe);
    cudaGetSymbolAddress((void**)&kv,   g_kv);
    cudaGetSymbolAddress((void**)&attn, g_attn);

    // 1) q_a = hidden @ Wqa   [2048 x 1536]
    gemm_kernel<<<dim3(QLR / 128, S_LEN / 128), 256>>>(
        qa, hidden, Wqa, S_LEN, QLR, HID, HID, QLR, QLR);
    // 2) ckv = hidden @ Wkva  [2048 x 576]
    gemm_kernel<<<dim3((CKVD + 127) / 128, S_LEN / 128), 256>>>(
        ckv, hidden, Wkva, S_LEN, CKVD, HID, HID, CKVD, CKVD);
    // 3) rmsnorm(q_a) in place
    rmsnorm_kernel<<<S_LEN, 256>>>(qa, qa, qa_ln, QLR, QLR, QLR);
    // 4) rmsnorm(c_kv) -> ckvn
    rmsnorm_kernel<<<S_LEN, 256>>>(ckvn, ckv, kv_ln, KVLR, CKVD, KVLR);
    // 5) q = q_a @ Wqb        [2048 x 3072]
    gemm_kernel<<<dim3((NH * QHD) / 128, S_LEN / 128), 256>>>(
        q, qa, Wqb, S_LEN, NH * QHD, QLR, QLR, NH * QHD, NH * QHD);
    // 6) kv = ckvn @ Wkvb     [2048 x 4096]
    gemm_kernel<<<dim3((NH * 256) / 128, S_LEN / 128), 256>>>(
        kv, ckvn, Wkvb, S_LEN, NH * 256, KVLR, KVLR, NH * 256, NH * 256);
    // 7) RoPE on q_pe (in place) and k_pe (ckv tail -> g_kpe)
    rope_kernel<<<S_LEN, (NH + 1) * 32>>>(q, kpe, ckv, pos);
    // 8) causal flash attention -> g_attn
    size_t fa_smem = (size_t)FA_SMEM_FLOATS * sizeof(float);
    cudaFuncSetAttribute(flash_kernel,
                         cudaFuncAttributeMaxDynamicSharedMemorySize, (int)fa_smem);
    flash_kernel<<<dim3(S_LEN / FA_BM, NH), 256, fa_smem>>>(attn, q, kv, kpe);
    // 9) out = attn @ Wo      [2048 x 2048]
    gemm_kernel<<<dim3(HID / 128, S_LEN / 128), 256>>>(
        out, attn, Wo, S_LEN, HID, NH * VD, NH * VD, HID, HID);
}

// round 6
// speedup vs baseline: 1.2971x; 1.2971x over previous
#include <cuda_runtime.h>
#include <cuda_bf16.h>
#include <math.h>
#include <stdint.h>

// ---------------------------------------------------------------------------
// Problem constants (DeepseekV3 MLA prefill, B=1, S=2048)
// ---------------------------------------------------------------------------
#define S_LEN  2048
#define HID    2048
#define NH     16
#define NOPE   128
#define ROPE_D 64
#define QHD    192     // NOPE + ROPE
#define VD     128
#define QLR    1536
#define KVLR   512
#define CKVD   576     // KVLR + ROPE

// ---------------------------------------------------------------------------
// Scratch (static __device__ arrays — no runtime allocation)
// ---------------------------------------------------------------------------
__device__ float g_qa  [S_LEN * QLR];
__device__ float g_q   [S_LEN * NH * QHD];
__device__ float g_ckv [S_LEN * CKVD];
__device__ float g_ckvn[S_LEN * KVLR];
__device__ float g_kpe [S_LEN * ROPE_D];
__device__ float g_kv  [S_LEN * NH * (NOPE + VD)];
__device__ float g_attn[S_LEN * NH * VD];

// ---------------------------------------------------------------------------
// 3xTF32 tensor-core GEMM: C[M,N] = A[M,K] @ B[K,N], fp32 in/out.
//   Block 128x128, K-chunk 32, 256 threads = 8 warps, warp tile 64x32.
//   Each input is split x = hi + lo (both tf32); D = aH*bH + aL*bH + aH*bL
//   with fp32 accumulators -> fp32-level accuracy at tensor-core speed.
// Requires: M % 128 == 0, K % 32 == 0. N guarded.
// Dynamic smem: AsH/AsL 128x36, BsH/BsL 32x136 (u32) = 71680 bytes.
// ---------------------------------------------------------------------------
#define GT_SMEM_BYTES ((128*36*2 + 32*136*2) * 4)

__device__ __forceinline__ uint32_t f2tf32(float x) {
    uint32_t r;
    asm("cvt.rna.tf32.f32 %0, %1;" : "=r"(r) : "f"(x));
    return r;
}

__device__ __forceinline__ void mma_tf32(float c[4], const uint32_t a[4],
                                         const uint32_t b[2]) {
    asm volatile(
        "mma.sync.aligned.m16n8k8.row.col.f32.tf32.tf32.f32 "
        "{%0,%1,%2,%3}, {%4,%5,%6,%7}, {%8,%9}, {%0,%1,%2,%3};"
        : "+f"(c[0]), "+f"(c[1]), "+f"(c[2]), "+f"(c[3])
        : "r"(a[0]), "r"(a[1]), "r"(a[2]), "r"(a[3]), "r"(b[0]), "r"(b[1]));
}

__global__ void __launch_bounds__(256, 2) gemm_tf32_kernel(
    float* __restrict__ C, const float* __restrict__ A, const float* __restrict__ B,
    int M, int N, int K, int lda, int ldb, int ldc)
{
    extern __shared__ uint32_t su[];
    uint32_t* AsH = su;                 // [128][36]
    uint32_t* AsL = AsH + 128 * 36;
    uint32_t* BsH = AsL + 128 * 36;     // [32][136]
    uint32_t* BsL = BsH + 32 * 136;

    const int tid  = threadIdx.x;
    const int lane = tid & 31;
    const int w    = tid >> 5;          // 0..7
    const int wm   = w >> 2;            // 0..1  (64-row slab)
    const int wn   = w & 3;             // 0..3  (32-col slab)
    const int g    = lane >> 2;         // 0..7
    const int t    = lane & 3;          // 0..3
    const int m0   = blockIdx.y * 128;
    const int n0   = blockIdx.x * 128;

    float acc[4][4][4];
#pragma unroll
    for (int mi = 0; mi < 4; mi++)
#pragma unroll
        for (int ni = 0; ni < 4; ni++)
#pragma unroll
            for (int e = 0; e < 4; e++) acc[mi][ni][e] = 0.f;

    for (int k0 = 0; k0 < K; k0 += 32) {
        // ---- load A tile 128x32 (split hi/lo) ----
#pragma unroll
        for (int it = 0; it < 4; it++) {
            int v  = tid + it * 256;     // 0..1023
            int r  = v >> 3;
            int c4 = (v & 7) * 4;
            float4 a = *(const float4*)(A + (size_t)(m0 + r) * lda + k0 + c4);
            float av[4] = {a.x, a.y, a.z, a.w};
#pragma unroll
            for (int e = 0; e < 4; e++) {
                uint32_t h = f2tf32(av[e]);
                uint32_t l = f2tf32(av[e] - __uint_as_float(h));
                AsH[r * 36 + c4 + e] = h;
                AsL[r * 36 + c4 + e] = l;
            }
        }
        // ---- load B tile 32x128 (split hi/lo, N guarded) ----
#pragma unroll
        for (int it = 0; it < 4; it++) {
            int v  = tid + it * 256;
            int k  = v >> 5;
            int c4 = (v & 31) * 4;
            int n  = n0 + c4;
            float4 b;
            if (n + 3 < N) {
                b = *(const float4*)(B + (size_t)(k0 + k) * ldb + n);
            } else {
                const float* bp = B + (size_t)(k0 + k) * ldb;
                b.x = (n + 0 < N) ? bp[n + 0] : 0.f;
                b.y = (n + 1 < N) ? bp[n + 1] : 0.f;
                b.z = (n + 2 < N) ? bp[n + 2] : 0.f;
                b.w = (n + 3 < N) ? bp[n + 3] : 0.f;
            }
            float bv[4] = {b.x, b.y, b.z, b.w};
#pragma unroll
            for (int e = 0; e < 4; e++) {
                uint32_t h = f2tf32(bv[e]);
                uint32_t l = f2tf32(bv[e] - __uint_as_float(h));
                BsH[k * 136 + c4 + e] = h;
                BsL[k * 136 + c4 + e] = l;
            }
        }
        __syncthreads();

        // ---- compute: 4 k-atoms of k8 ----
#pragma unroll
        for (int kk = 0; kk < 4; kk++) {
            const int kb = kk * 8;
            uint32_t bH[4][2], bL[4][2];
#pragma unroll
            for (int ni = 0; ni < 4; ni++) {
                int cn = wn * 32 + ni * 8 + g;
                bH[ni][0] = BsH[(kb + t)     * 136 + cn];
                bH[ni][1] = BsH[(kb + t + 4) * 136 + cn];
                bL[ni][0] = BsL[(kb + t)     * 136 + cn];
                bL[ni][1] = BsL[(kb + t + 4) * 136 + cn];
            }
#pragma unroll
            for (int mi = 0; mi < 4; mi++) {
                const int rm = wm * 64 + mi * 16;
                uint32_t aH[4], aL[4];
                aH[0] = AsH[(rm + g)     * 36 + kb + t];
                aH[1] = AsH[(rm + g + 8) * 36 + kb + t];
                aH[2] = AsH[(rm + g)     * 36 + kb + t + 4];
                aH[3] = AsH[(rm + g + 8) * 36 + kb + t + 4];
                aL[0] = AsL[(rm + g)     * 36 + kb + t];
                aL[1] = AsL[(rm + g + 8) * 36 + kb + t];
                aL[2] = AsL[(rm + g)     * 36 + kb + t + 4];
                aL[3] = AsL[(rm + g + 8) * 36 + kb + t + 4];
#pragma unroll
                for (int ni = 0; ni < 4; ni++) {
                    mma_tf32(acc[mi][ni], aH, bH[ni]);
                    mma_tf32(acc[mi][ni], aL, bH[ni]);
                    mma_tf32(acc[mi][ni], aH, bL[ni]);
                }
            }
        }
        __syncthreads();
    }

    // ---- epilogue ----
#pragma unroll
    for (int mi = 0; mi < 4; mi++) {
        int r0 = m0 + wm * 64 + mi * 16 + g;
        int r1 = r0 + 8;
#pragma unroll
        for (int ni = 0; ni < 4; ni++) {
            int c = n0 + wn * 32 + ni * 8 + 2 * t;
            if (c < N) {  // N even, c even -> c and c+1 valid together
                *(float2*)(C + (size_t)r0 * ldc + c) =
                    make_float2(acc[mi][ni][0], acc[mi][ni][1]);
                *(float2*)(C + (size_t)r1 * ldc + c) =
                    make_float2(acc[mi][ni][2], acc[mi][ni][3]);
            }
        }
    }
}

// ---------------------------------------------------------------------------
// RMSNorm: one block per row.
// ---------------------------------------------------------------------------
__global__ void __launch_bounds__(256) rmsnorm_kernel(
    float* __restrict__ out, const float* __restrict__ in,
    const float* __restrict__ w, int D, int ldin, int ldout)
{
    const int row = blockIdx.x;
    const float* x = in + (size_t)row * ldin;
    float* y = out + (size_t)row * ldout;

    float s = 0.f;
    for (int i = threadIdx.x; i < D; i += 256) {
        float v = x[i];
        s += v * v;
    }
#pragma unroll
    for (int o = 16; o; o >>= 1) s += __shfl_xor_sync(0xffffffffu, s, o);

    __shared__ float red[8];
    __shared__ float inv_s;
    if ((threadIdx.x & 31) == 0) red[threadIdx.x >> 5] = s;
    __syncthreads();
    if (threadIdx.x == 0) {
        float tt = 0.f;
#pragma unroll
        for (int i = 0; i < 8; i++) tt += red[i];
        inv_s = rsqrtf(tt / (float)D + 1e-6f);
    }
    __syncthreads();
    float inv = inv_s;
    for (int i = threadIdx.x; i < D; i += 256) y[i] = w[i] * (x[i] * inv);
}

// ---------------------------------------------------------------------------
// RoPE (deinterleave + rotate_half fused).
// ---------------------------------------------------------------------------
__global__ void rope_kernel(float* __restrict__ q, float* __restrict__ kpe,
                            const float* __restrict__ ckv,
                            const int* __restrict__ pos_ids)
{
    const int srow = blockIdx.x;
    const int tid  = threadIdx.x;
    const int j    = tid & 31;

    const float pos  = (float)pos_ids[srow];
    const float freq = __expf(-((2.f * (float)j) / 64.f) * logf(10000.f));
    const float ang  = pos * freq;
    float cv, sv;
    __sincosf(ang, &sv, &cv);

    if (tid < NH * 32) {
        const int h = tid >> 5;
        float* base = q + (size_t)srow * (NH * QHD) + h * QHD + NOPE;
        float x0 = base[2 * j];
        float x1 = base[2 * j + 1];
        __syncwarp();
        base[j]      = x0 * cv - x1 * sv;
        base[32 + j] = x1 * cv + x0 * sv;
    } else {
        const float* src = ckv + (size_t)srow * CKVD + KVLR;
        float x0 = src[2 * j];
        float x1 = src[2 * j + 1];
        float* dst = kpe + (size_t)srow * ROPE_D;
        dst[j]      = x0 * cv - x1 * sv;
        dst[32 + j] = x1 * cv + x0 * sv;
    }
}

// ---------------------------------------------------------------------------
// Causal flash attention, fp32 (unchanged from passing R5 kernel).
// ---------------------------------------------------------------------------
#define FA_BM 64
#define FA_BN 64
#define FA_D  192
#define FA_DP 196
#define FA_DV 128
#define FA_SMEM_FLOATS (FA_BM*FA_DP + FA_BN*FA_DP + FA_BN*FA_DV + FA_BM*FA_BN)

__global__ void __launch_bounds__(256) flash_kernel(
    float* __restrict__ O, const float* __restrict__ Q,
    const float* __restrict__ KV, const float* __restrict__ KPE)
{
    extern __shared__ float sm[];
    float* sQ = sm;
    float* sK = sQ + FA_BM * FA_DP;
    float* sV = sK + FA_BN * FA_DP;
    float* sP = sV + FA_BN * FA_DV;

    const int tid = threadIdx.x;
    const int tx  = tid & 15;
    const int ty  = tid >> 4;
    const int h   = blockIdx.y;
    const int qb  = blockIdx.x;
    const int q0  = qb * FA_BM;

    for (int v = tid; v < FA_BM * 48; v += 256) {
        int r = v / 48, cc = v % 48;
        float4 val = *(const float4*)(Q + (size_t)(q0 + r) * (NH * QHD) + h * QHD + cc * 4);
        *(float4*)(sQ + r * FA_DP + cc * 4) = val;
    }

    float acc[4][8];
    float m_i[4], l_i[4];
#pragma unroll
    for (int i = 0; i < 4; i++) {
        m_i[i] = -1e30f;
        l_i[i] = 0.f;
#pragma unroll
        for (int j = 0; j < 8; j++) acc[i][j] = 0.f;
    }
    const float scale = rsqrtf((float)QHD);

    for (int kb = 0; kb <= qb; kb++) {
        const int k0 = kb * FA_BN;
        __syncthreads();
        for (int v = tid; v < FA_BN * 48; v += 256) {
            int r = v / 48, cc = v % 48;
            float4 val;
            if (cc < 32)
                val = *(const float4*)(KV + (size_t)(k0 + r) * (NH * 256) + h * 256 + cc * 4);
            else
                val = *(const float4*)(KPE + (size_t)(k0 + r) * ROPE_D + (cc - 32) * 4);
            *(float4*)(sK + r * FA_DP + cc * 4) = val;
        }
        for (int v = tid; v < FA_BN * 32; v += 256) {
            int r = v / 32, cc = v % 32;
            float4 val = *(const float4*)(KV + (size_t)(k0 + r) * (NH * 256) + h * 256 + NOPE + cc * 4);
            *(float4*)(sV + r * FA_DV + cc * 4) = val;
        }
        __syncthreads();

        float s4[4][4];
#pragma unroll
        for (int i = 0; i < 4; i++)
#pragma unroll
            for (int j = 0; j < 4; j++) s4[i][j] = 0.f;

#pragma unroll 4
        for (int d = 0; d < FA_D; d += 4) {
            float4 qv[4], kv4[4];
#pragma unroll
            for (int i = 0; i < 4; i++) qv[i]  = *(float4*)(sQ + (ty * 4 + i) * FA_DP + d);
#pragma unroll
            for (int j = 0; j < 4; j++) kv4[j] = *(float4*)(sK + (tx * 4 + j) * FA_DP + d);
#pragma unroll
            for (int i = 0; i < 4; i++)
#pragma unroll
                for (int j = 0; j < 4; j++)
                    s4[i][j] += qv[i].x * kv4[j].x + qv[i].y * kv4[j].y
                              + qv[i].z * kv4[j].z + qv[i].w * kv4[j].w;
        }

#pragma unroll
        for (int i = 0; i < 4; i++) {
            const int qi = q0 + ty * 4 + i;
            float rmax = -1e30f;
#pragma unroll
            for (int j = 0; j < 4; j++) {
                int kj = k0 + tx * 4 + j;
                float v = (kj <= qi) ? s4[i][j] * scale : -1e30f;
                s4[i][j] = v;
                rmax = fmaxf(rmax, v);
            }
#pragma unroll
            for (int o = 8; o; o >>= 1)
                rmax = fmaxf(rmax, __shfl_xor_sync(0xffffffffu, rmax, o, 16));

            float m_new = fmaxf(m_i[i], rmax);
            float alpha = __expf(m_i[i] - m_new);
            float rsum = 0.f;
#pragma unroll
            for (int j = 0; j < 4; j++) {
                float p = __expf(s4[i][j] - m_new);
                s4[i][j] = p;
                rsum += p;
            }
#pragma unroll
            for (int o = 8; o; o >>= 1)
                rsum += __shfl_xor_sync(0xffffffffu, rsum, o, 16);

            l_i[i] = l_i[i] * alpha + rsum;
            m_i[i] = m_new;
#pragma unroll
            for (int j = 0; j < 8; j++) acc[i][j] *= alpha;
#pragma unroll
            for (int j = 0; j < 4; j++)
                sP[(ty * 4 + i) * FA_BN + tx * 4 + j] = s4[i][j];
        }
        __syncthreads();

#pragma unroll 4
        for (int kc = 0; kc < FA_BN; kc++) {
            float4 v0 = *(float4*)(sV + kc * FA_DV + tx * 8);
            float4 v1 = *(float4*)(sV + kc * FA_DV + tx * 8 + 4);
#pragma unroll
            for (int i = 0; i < 4; i++) {
                float p = sP[(ty * 4 + i) * FA_BN + kc];
                acc[i][0] += p * v0.x; acc[i][1] += p * v0.y;
                acc[i][2] += p * v0.z; acc[i][3] += p * v0.w;
                acc[i][4] += p * v1.x; acc[i][5] += p * v1.y;
                acc[i][6] += p * v1.z; acc[i][7] += p * v1.w;
            }
        }
    }

#pragma unroll
    for (int i = 0; i < 4; i++) {
        float inv_l = 1.f / l_i[i];
        float* op = O + (size_t)(q0 + ty * 4 + i) * (NH * VD) + h * VD + tx * 8;
#pragma unroll
        for (int j = 0; j < 8; j++) op[j] = acc[i][j] * inv_l;
    }
}

// ---------------------------------------------------------------------------
// Launch
// ---------------------------------------------------------------------------
extern "C" void kernel_launch(void* const* d_in, const int* in_sizes, int n_in,
                              void* d_out, int out_size)
{
    const float* hidden = (const float*)d_in[0];
    const int*   pos    = (const int*)d_in[1];
    const float* Wqa    = (const float*)d_in[2];
    const float* qa_ln  = (const float*)d_in[3];
    const float* Wqb    = (const float*)d_in[4];
    const float* Wkva   = (const float*)d_in[5];
    const float* kv_ln  = (const float*)d_in[6];
    const float* Wkvb   = (const float*)d_in[7];
    const float* Wo     = (const float*)d_in[8];
    float* out = (float*)d_out;

    float *qa, *q, *ckv, *ckvn, *kpe, *kv, *attn;
    cudaGetSymbolAddress((void**)&qa,   g_qa);
    cudaGetSymbolAddress((void**)&q,    g_q);
    cudaGetSymbolAddress((void**)&ckv,  g_ckv);
    cudaGetSymbolAddress((void**)&ckvn, g_ckvn);
    cudaGetSymbolAddress((void**)&kpe,  g_kpe);
    cudaGetSymbolAddress((void**)&kv,   g_kv);
    cudaGetSymbolAddress((void**)&attn, g_attn);

    cudaFuncSetAttribute(gemm_tf32_kernel,
                         cudaFuncAttributeMaxDynamicSharedMemorySize, GT_SMEM_BYTES);

    // 1) q_a = hidden @ Wqa   [2048 x 1536]
    gemm_tf32_kernel<<<dim3(QLR / 128, S_LEN / 128), 256, GT_SMEM_BYTES>>>(
        qa, hidden, Wqa, S_LEN, QLR, HID, HID, QLR, QLR);
    // 2) ckv = hidden @ Wkva  [2048 x 576]
    gemm_tf32_kernel<<<dim3((CKVD + 127) / 128, S_LEN / 128), 256, GT_SMEM_BYTES>>>(
        ckv, hidden, Wkva, S_LEN, CKVD, HID, HID, CKVD, CKVD);
    // 3) rmsnorm(q_a) in place
    rmsnorm_kernel<<<S_LEN, 256>>>(qa, qa, qa_ln, QLR, QLR, QLR);
    // 4) rmsnorm(c_kv) -> ckvn
    rmsnorm_kernel<<<S_LEN, 256>>>(ckvn, ckv, kv_ln, KVLR, CKVD, KVLR);
    // 5) q = q_a @ Wqb        [2048 x 3072]
    gemm_tf32_kernel<<<dim3((NH * QHD) / 128, S_LEN / 128), 256, GT_SMEM_BYTES>>>(
        q, qa, Wqb, S_LEN, NH * QHD, QLR, QLR, NH * QHD, NH * QHD);
    // 6) kv = ckvn @ Wkvb     [2048 x 4096]
    gemm_tf32_kernel<<<dim3((NH * 256) / 128, S_LEN / 128), 256, GT_SMEM_BYTES>>>(
        kv, ckvn, Wkvb, S_LEN, NH * 256, KVLR, KVLR, NH * 256, NH * 256);
    // 7) RoPE on q_pe (in place) and k_pe (ckv tail -> g_kpe)
    rope_kernel<<<S_LEN, (NH + 1) * 32>>>(q, kpe, ckv, pos);
    // 8) causal flash attention -> g_attn
    size_t fa_smem = (size_t)FA_SMEM_FLOATS * sizeof(float);
    cudaFuncSetAttribute(flash_kernel,
                         cudaFuncAttributeMaxDynamicSharedMemorySize, (int)fa_smem);
    flash_kernel<<<dim3(S_LEN / FA_BM, NH), 256, fa_smem>>>(attn, q, kv, kpe);
    // 9) out = attn @ Wo      [2048 x 2048]
    gemm_tf32_kernel<<<dim3(HID / 128, S_LEN / 128), 256, GT_SMEM_BYTES>>>(
        out, attn, Wo, S_LEN, HID, NH * VD, NH * VD, HID, HID);
}

// round 7
// speedup vs baseline: 1.6331x; 1.2590x over previous
#include <cuda_runtime.h>
#include <cuda_bf16.h>
#include <math.h>
#include <stdint.h>

// ---------------------------------------------------------------------------
// Problem constants (DeepseekV3 MLA prefill, B=1, S=2048)
// ---------------------------------------------------------------------------
#define S_LEN  2048
#define HID    2048
#define NH     16
#define NOPE   128
#define ROPE_D 64
#define QHD    192
#define VD     128
#define QLR    1536
#define KVLR   512
#define CKVD   576

// ---------------------------------------------------------------------------
// Scratch (static __device__ arrays — no runtime allocation)
// ---------------------------------------------------------------------------
__device__ float g_qa  [S_LEN * QLR];          // GEMM1 out (fp32)
__device__ float g_q   [S_LEN * NH * QHD];     // GEMM5 out, RoPE in place
__device__ float g_ckv [S_LEN * CKVD];         // GEMM2 out (fp32)
__device__ float g_kpe [S_LEN * ROPE_D];
__device__ float g_kv  [S_LEN * NH * (NOPE + VD)];
__device__ float g_attn[S_LEN * NH * VD];

// Packed bf16 hi/lo activations (u32 = two K-adjacent bf16, lo half = even k)
__device__ uint32_t g_hidh [S_LEN * (HID/2)];
__device__ uint32_t g_hidl [S_LEN * (HID/2)];
__device__ uint32_t g_qanh [S_LEN * (QLR/2)];
__device__ uint32_t g_qanl [S_LEN * (QLR/2)];
__device__ uint32_t g_ckvnh[S_LEN * (KVLR/2)];
__device__ uint32_t g_ckvnl[S_LEN * (KVLR/2)];
__device__ uint32_t g_attnh[S_LEN * (NH*VD/2)];
__device__ uint32_t g_attnl[S_LEN * (NH*VD/2)];

// Transposed + split weights: [Npad][K/2] words
__device__ uint32_t g_Wqath [1536 * (HID/2)];
__device__ uint32_t g_Wqatl [1536 * (HID/2)];
__device__ uint32_t g_Wkvath[ 640 * (HID/2)];   // Npad(576)=640
__device__ uint32_t g_Wkvatl[ 640 * (HID/2)];
__device__ uint32_t g_Wqbth [3072 * (QLR/2)];
__device__ uint32_t g_Wqbtl [3072 * (QLR/2)];
__device__ uint32_t g_Wkvbth[4096 * (KVLR/2)];
__device__ uint32_t g_Wkvbtl[4096 * (KVLR/2)];
__device__ uint32_t g_Woth  [2048 * (NH*VD/2)];
__device__ uint32_t g_Wotl  [2048 * (NH*VD/2)];

// ---------------------------------------------------------------------------
// bf16 hi/lo split helpers
// ---------------------------------------------------------------------------
__device__ __forceinline__ void split2(float a, float b, uint32_t& hi, uint32_t& lo) {
    __nv_bfloat16 ah = __float2bfloat16(a);
    __nv_bfloat16 bh = __float2bfloat16(b);
    __nv_bfloat16 al = __float2bfloat16(a - __bfloat162float(ah));
    __nv_bfloat16 bl = __float2bfloat16(b - __bfloat162float(bh));
    hi = (uint32_t)__bfloat16_as_ushort(ah) | ((uint32_t)__bfloat16_as_ushort(bh) << 16);
    lo = (uint32_t)__bfloat16_as_ushort(al) | ((uint32_t)__bfloat16_as_ushort(bl) << 16);
}

// ---------------------------------------------------------------------------
// Weight transpose + split: W[K][N] (ld=N) -> Th/Tl[Npad][K/2] words.
// block (32,8), grid (Npad/32, K/32). Pad rows (n>=N) become zeros.
// ---------------------------------------------------------------------------
__global__ void __launch_bounds__(256) wt_split_kernel(
    uint32_t* __restrict__ Th, uint32_t* __restrict__ Tl,
    const float* __restrict__ W, int K, int N)
{
    __shared__ float t[32][33];
    const int n0 = blockIdx.x * 32;
    const int k0 = blockIdx.y * 32;
    const int tx = threadIdx.x, ty = threadIdx.y;
    const int n = n0 + tx;
#pragma unroll
    for (int i = 0; i < 4; i++) {
        int k = ty + i * 8;
        t[k][tx] = (n < N) ? W[(size_t)(k0 + k) * N + n] : 0.f;
    }
    __syncthreads();
    const int Kw = K >> 1;
#pragma unroll
    for (int it = 0; it < 2; it++) {
        int s  = ty * 32 + tx + it * 256;
        int nl = s >> 4, wd = s & 15;
        uint32_t hi, lo;
        split2(t[2 * wd][nl], t[2 * wd + 1][nl], hi, lo);
        size_t o = (size_t)(n0 + nl) * Kw + (k0 >> 1) + wd;
        Th[o] = hi;
        Tl[o] = lo;
    }
}

// ---------------------------------------------------------------------------
// Activation split (no transpose): x[nWords*2 floats] -> hi/lo words
// ---------------------------------------------------------------------------
__global__ void split_pack_kernel(uint32_t* __restrict__ oh, uint32_t* __restrict__ ol,
                                  const float* __restrict__ x, int nWords)
{
    int i = blockIdx.x * 256 + threadIdx.x;
    if (i < nWords) {
        float2 v = ((const float2*)x)[i];
        uint32_t hi, lo;
        split2(v.x, v.y, hi, lo);
        oh[i] = hi;
        ol[i] = lo;
    }
}

// ---------------------------------------------------------------------------
// RMSNorm fused with hi/lo pack: out words [row][D/2]
// ---------------------------------------------------------------------------
__global__ void __launch_bounds__(256) rmsnorm_pack_kernel(
    uint32_t* __restrict__ oh, uint32_t* __restrict__ ol,
    const float* __restrict__ in, const float* __restrict__ w, int D, int ldin)
{
    const int row = blockIdx.x;
    const float* x = in + (size_t)row * ldin;

    float s = 0.f;
    for (int i = threadIdx.x; i < D; i += 256) {
        float v = x[i];
        s += v * v;
    }
#pragma unroll
    for (int o = 16; o; o >>= 1) s += __shfl_xor_sync(0xffffffffu, s, o);
    __shared__ float red[8];
    __shared__ float inv_s;
    if ((threadIdx.x & 31) == 0) red[threadIdx.x >> 5] = s;
    __syncthreads();
    if (threadIdx.x == 0) {
        float tt = 0.f;
#pragma unroll
        for (int i = 0; i < 8; i++) tt += red[i];
        inv_s = rsqrtf(tt / (float)D + 1e-6f);
    }
    __syncthreads();
    const float inv = inv_s;
    const int Dw = D >> 1;
    for (int i = threadIdx.x; i < Dw; i += 256) {
        float a = w[2 * i]     * (x[2 * i]     * inv);
        float b = w[2 * i + 1] * (x[2 * i + 1] * inv);
        uint32_t hi, lo;
        split2(a, b, hi, lo);
        oh[(size_t)row * Dw + i] = hi;
        ol[(size_t)row * Dw + i] = lo;
    }
}

// ---------------------------------------------------------------------------
// 3-term bf16 tensor GEMM: C[M][N] fp32 = A @ B with pre-split inputs.
//   A as Ah/Al [M][K/2] words; B as Bh/Bl [Npad][K/2] words (transposed).
//   Block 128x128, K-chunk 32, 256 thr = 8 warps (warp tile 64x32),
//   mma.m16n8k16.bf16, 2-stage cp.async pipeline.
// smem per stage: 4 arrays x 128 rows x 20 words (16 used, pad 4) = 40960 B.
// ---------------------------------------------------------------------------
#define GS_STAGE_WORDS 10240
#define GEMM_SMEM_BYTES (2 * GS_STAGE_WORDS * 4)

__device__ __forceinline__ void mma_bf16(float c[4], const uint32_t a[4],
                                         const uint32_t b[2]) {
    asm volatile(
        "mma.sync.aligned.m16n8k16.row.col.f32.bf16.bf16.f32 "
        "{%0,%1,%2,%3}, {%4,%5,%6,%7}, {%8,%9}, {%0,%1,%2,%3};"
        : "+f"(c[0]), "+f"(c[1]), "+f"(c[2]), "+f"(c[3])
        : "r"(a[0]), "r"(a[1]), "r"(a[2]), "r"(a[3]), "r"(b[0]), "r"(b[1]));
}

#define CP16(dst, src) \
    asm volatile("cp.async.cg.shared.global [%0], [%1], 16;" :: "r"(dst), "l"(src))

__global__ void __launch_bounds__(256, 2) gemm_bf16x3_kernel(
    float* __restrict__ C,
    const uint32_t* __restrict__ Ah, const uint32_t* __restrict__ Al,
    const uint32_t* __restrict__ Bh, const uint32_t* __restrict__ Bl,
    int M, int N, int K, int ldc)
{
    extern __shared__ uint32_t sw[];
    const int Kw  = K >> 1;
    const int tid = threadIdx.x;
    const int lane = tid & 31;
    const int w   = tid >> 5;
    const int wm  = w >> 2;
    const int wn  = w & 3;
    const int g   = lane >> 2;
    const int t   = lane & 3;
    const int m0  = blockIdx.y * 128;
    const int n0  = blockIdx.x * 128;
    const uint32_t sbase = (uint32_t)__cvta_generic_to_shared(sw);

    // load slots: two per thread per array; slot s: row = s>>2, word4 = (s&3)*4
    const int r0 = tid >> 2,          c0 = (tid & 3) * 4;
    const int r1 = (tid + 256) >> 2,  c1 = ((tid + 256) & 3) * 4;

    float acc[4][4][4];
#pragma unroll
    for (int mi = 0; mi < 4; mi++)
#pragma unroll
        for (int ni = 0; ni < 4; ni++)
#pragma unroll
            for (int e = 0; e < 4; e++) acc[mi][ni][e] = 0.f;

    const int nchunks = K / 32;

#define LOAD_CHUNK(ch, stage)                                                    \
    do {                                                                         \
        const int kw0 = (ch) * 16;                                               \
        uint32_t sb = sbase + (stage) * (GS_STAGE_WORDS * 4);                    \
        uint32_t dA0 = sb + (r0 * 20 + c0) * 4;                                  \
        uint32_t dA1 = sb + (r1 * 20 + c1) * 4;                                  \
        uint32_t dB0 = sb + (5120 + r0 * 20 + c0) * 4;                           \
        uint32_t dB1 = sb + (5120 + r1 * 20 + c1) * 4;                           \
        CP16(dA0,          Ah + (size_t)(m0 + r0) * Kw + kw0 + c0);              \
        CP16(dA1,          Ah + (size_t)(m0 + r1) * Kw + kw0 + c1);              \
        CP16(dA0 + 10240,  Al + (size_t)(m0 + r0) * Kw + kw0 + c0);              \
        CP16(dA1 + 10240,  Al + (size_t)(m0 + r1) * Kw + kw0 + c1);              \
        CP16(dB0,          Bh + (size_t)(n0 + r0) * Kw + kw0 + c0);              \
        CP16(dB1,          Bh + (size_t)(n0 + r1) * Kw + kw0 + c1);              \
        CP16(dB0 + 10240,  Bl + (size_t)(n0 + r0) * Kw + kw0 + c0);              \
        CP16(dB1 + 10240,  Bl + (size_t)(n0 + r1) * Kw + kw0 + c1);              \
    } while (0)

    LOAD_CHUNK(0, 0);
    asm volatile("cp.async.commit_group;");

    for (int ch = 0; ch < nchunks; ch++) {
        if (ch + 1 < nchunks) {
            LOAD_CHUNK(ch + 1, (ch + 1) & 1);
            asm volatile("cp.async.commit_group;");
            asm volatile("cp.async.wait_group 1;");
        } else {
            asm volatile("cp.async.wait_group 0;");
        }
        __syncthreads();

        const uint32_t* st  = sw + (ch & 1) * GS_STAGE_WORDS;
        const uint32_t* sAh = st;
        const uint32_t* sAl = st + 2560;
        const uint32_t* sBh = st + 5120;
        const uint32_t* sBl = st + 7680;

#pragma unroll
        for (int kk = 0; kk < 2; kk++) {
            const int off = kk * 8;
            uint32_t bh[4][2], bl[4][2];
#pragma unroll
            for (int ni = 0; ni < 4; ni++) {
                int ba = (wn * 32 + ni * 8 + g) * 20 + off + t;
                bh[ni][0] = sBh[ba];
                bh[ni][1] = sBh[ba + 4];
                bl[ni][0] = sBl[ba];
                bl[ni][1] = sBl[ba + 4];
            }
#pragma unroll
            for (int mi = 0; mi < 4; mi++) {
                int aa = (wm * 64 + mi * 16 + g) * 20 + off + t;
                uint32_t ah[4], al[4];
                ah[0] = sAh[aa];       ah[1] = sAh[aa + 160];
                ah[2] = sAh[aa + 4];   ah[3] = sAh[aa + 164];
                al[0] = sAl[aa];       al[1] = sAl[aa + 160];
                al[2] = sAl[aa + 4];   al[3] = sAl[aa + 164];
#pragma unroll
                for (int ni = 0; ni < 4; ni++) {
                    mma_bf16(acc[mi][ni], ah, bh[ni]);
                    mma_bf16(acc[mi][ni], al, bh[ni]);
                    mma_bf16(acc[mi][ni], ah, bl[ni]);
                }
            }
        }
        __syncthreads();
    }
#undef LOAD_CHUNK

    // epilogue
#pragma unroll
    for (int mi = 0; mi < 4; mi++) {
        int rr0 = m0 + wm * 64 + mi * 16 + g;
        int rr1 = rr0 + 8;
#pragma unroll
        for (int ni = 0; ni < 4; ni++) {
            int c = n0 + wn * 32 + ni * 8 + 2 * t;
            if (c < N) {
                *(float2*)(C + (size_t)rr0 * ldc + c) =
                    make_float2(acc[mi][ni][0], acc[mi][ni][1]);
                *(float2*)(C + (size_t)rr1 * ldc + c) =
                    make_float2(acc[mi][ni][2], acc[mi][ni][3]);
            }
        }
    }
}

// ---------------------------------------------------------------------------
// RoPE (deinterleave + rotate_half fused)
// ---------------------------------------------------------------------------
__global__ void rope_kernel(float* __restrict__ q, float* __restrict__ kpe,
                            const float* __restrict__ ckv,
                            const int* __restrict__ pos_ids)
{
    const int srow = blockIdx.x;
    const int tid  = threadIdx.x;
    const int j    = tid & 31;

    const float pos  = (float)pos_ids[srow];
    const float freq = __expf(-((2.f * (float)j) / 64.f) * logf(10000.f));
    const float ang  = pos * freq;
    float cv, sv;
    __sincosf(ang, &sv, &cv);

    if (tid < NH * 32) {
        const int h = tid >> 5;
        float* base = q + (size_t)srow * (NH * QHD) + h * QHD + NOPE;
        float x0 = base[2 * j];
        float x1 = base[2 * j + 1];
        __syncwarp();
        base[j]      = x0 * cv - x1 * sv;
        base[32 + j] = x1 * cv + x0 * sv;
    } else {
        const float* src = ckv + (size_t)srow * CKVD + KVLR;
        float x0 = src[2 * j];
        float x1 = src[2 * j + 1];
        float* dst = kpe + (size_t)srow * ROPE_D;
        dst[j]      = x0 * cv - x1 * sv;
        dst[32 + j] = x1 * cv + x0 * sv;
    }
}

// ---------------------------------------------------------------------------
// Causal flash attention, fp32 (unchanged — R8 target)
// ---------------------------------------------------------------------------
#define FA_BM 64
#define FA_BN 64
#define FA_D  192
#define FA_DP 196
#define FA_DV 128
#define FA_SMEM_FLOATS (FA_BM*FA_DP + FA_BN*FA_DP + FA_BN*FA_DV + FA_BM*FA_BN)

__global__ void __launch_bounds__(256) flash_kernel(
    float* __restrict__ O, const float* __restrict__ Q,
    const float* __restrict__ KV, const float* __restrict__ KPE)
{
    extern __shared__ float sm[];
    float* sQ = sm;
    float* sK = sQ + FA_BM * FA_DP;
    float* sV = sK + FA_BN * FA_DP;
    float* sP = sV + FA_BN * FA_DV;

    const int tid = threadIdx.x;
    const int tx  = tid & 15;
    const int ty  = tid >> 4;
    const int h   = blockIdx.y;
    const int qb  = blockIdx.x;
    const int q0  = qb * FA_BM;

    for (int v = tid; v < FA_BM * 48; v += 256) {
        int r = v / 48, cc = v % 48;
        float4 val = *(const float4*)(Q + (size_t)(q0 + r) * (NH * QHD) + h * QHD + cc * 4);
        *(float4*)(sQ + r * FA_DP + cc * 4) = val;
    }

    float acc[4][8];
    float m_i[4], l_i[4];
#pragma unroll
    for (int i = 0; i < 4; i++) {
        m_i[i] = -1e30f;
        l_i[i] = 0.f;
#pragma unroll
        for (int j = 0; j < 8; j++) acc[i][j] = 0.f;
    }
    const float scale = rsqrtf((float)QHD);

    for (int kb = 0; kb <= qb; kb++) {
        const int k0 = kb * FA_BN;
        __syncthreads();
        for (int v = tid; v < FA_BN * 48; v += 256) {
            int r = v / 48, cc = v % 48;
            float4 val;
            if (cc < 32)
                val = *(const float4*)(KV + (size_t)(k0 + r) * (NH * 256) + h * 256 + cc * 4);
            else
                val = *(const float4*)(KPE + (size_t)(k0 + r) * ROPE_D + (cc - 32) * 4);
            *(float4*)(sK + r * FA_DP + cc * 4) = val;
        }
        for (int v = tid; v < FA_BN * 32; v += 256) {
            int r = v / 32, cc = v % 32;
            float4 val = *(const float4*)(KV + (size_t)(k0 + r) * (NH * 256) + h * 256 + NOPE + cc * 4);
            *(float4*)(sV + r * FA_DV + cc * 4) = val;
        }
        __syncthreads();

        float s4[4][4];
#pragma unroll
        for (int i = 0; i < 4; i++)
#pragma unroll
            for (int j = 0; j < 4; j++) s4[i][j] = 0.f;

#pragma unroll 4
        for (int d = 0; d < FA_D; d += 4) {
            float4 qv[4], kv4[4];
#pragma unroll
            for (int i = 0; i < 4; i++) qv[i]  = *(float4*)(sQ + (ty * 4 + i) * FA_DP + d);
#pragma unroll
            for (int j = 0; j < 4; j++) kv4[j] = *(float4*)(sK + (tx * 4 + j) * FA_DP + d);
#pragma unroll
            for (int i = 0; i < 4; i++)
#pragma unroll
                for (int j = 0; j < 4; j++)
                    s4[i][j] += qv[i].x * kv4[j].x + qv[i].y * kv4[j].y
                              + qv[i].z * kv4[j].z + qv[i].w * kv4[j].w;
        }

#pragma unroll
        for (int i = 0; i < 4; i++) {
            const int qi = q0 + ty * 4 + i;
            float rmax = -1e30f;
#pragma unroll
            for (int j = 0; j < 4; j++) {
                int kj = k0 + tx * 4 + j;
                float v = (kj <= qi) ? s4[i][j] * scale : -1e30f;
                s4[i][j] = v;
                rmax = fmaxf(rmax, v);
            }
#pragma unroll
            for (int o = 8; o; o >>= 1)
                rmax = fmaxf(rmax, __shfl_xor_sync(0xffffffffu, rmax, o, 16));

            float m_new = fmaxf(m_i[i], rmax);
            float alpha = __expf(m_i[i] - m_new);
            float rsum = 0.f;
#pragma unroll
            for (int j = 0; j < 4; j++) {
                float p = __expf(s4[i][j] - m_new);
                s4[i][j] = p;
                rsum += p;
            }
#pragma unroll
            for (int o = 8; o; o >>= 1)
                rsum += __shfl_xor_sync(0xffffffffu, rsum, o, 16);

            l_i[i] = l_i[i] * alpha + rsum;
            m_i[i] = m_new;
#pragma unroll
            for (int j = 0; j < 8; j++) acc[i][j] *= alpha;
#pragma unroll
            for (int j = 0; j < 4; j++)
                sP[(ty * 4 + i) * FA_BN + tx * 4 + j] = s4[i][j];
        }
        __syncthreads();

#pragma unroll 4
        for (int kc = 0; kc < FA_BN; kc++) {
            float4 v0 = *(float4*)(sV + kc * FA_DV + tx * 8);
            float4 v1 = *(float4*)(sV + kc * FA_DV + tx * 8 + 4);
#pragma unroll
            for (int i = 0; i < 4; i++) {
                float p = sP[(ty * 4 + i) * FA_BN + kc];
                acc[i][0] += p * v0.x; acc[i][1] += p * v0.y;
                acc[i][2] += p * v0.z; acc[i][3] += p * v0.w;
                acc[i][4] += p * v1.x; acc[i][5] += p * v1.y;
                acc[i][6] += p * v1.z; acc[i][7] += p * v1.w;
            }
        }
    }

#pragma unroll
    for (int i = 0; i < 4; i++) {
        float inv_l = 1.f / l_i[i];
        float* op = O + (size_t)(q0 + ty * 4 + i) * (NH * VD) + h * VD + tx * 8;
#pragma unroll
        for (int j = 0; j < 8; j++) op[j] = acc[i][j] * inv_l;
    }
}

// ---------------------------------------------------------------------------
// Launch
// ---------------------------------------------------------------------------
extern "C" void kernel_launch(void* const* d_in, const int* in_sizes, int n_in,
                              void* d_out, int out_size)
{
    const float* hidden = (const float*)d_in[0];
    const int*   pos    = (const int*)d_in[1];
    const float* Wqa    = (const float*)d_in[2];
    const float* qa_ln  = (const float*)d_in[3];
    const float* Wqb    = (const float*)d_in[4];
    const float* Wkva   = (const float*)d_in[5];
    const float* kv_ln  = (const float*)d_in[6];
    const float* Wkvb   = (const float*)d_in[7];
    const float* Wo     = (const float*)d_in[8];
    float* out = (float*)d_out;

    float *qa, *q, *ckv, *kpe, *kv, *attn;
    cudaGetSymbolAddress((void**)&qa,   g_qa);
    cudaGetSymbolAddress((void**)&q,    g_q);
    cudaGetSymbolAddress((void**)&ckv,  g_ckv);
    cudaGetSymbolAddress((void**)&kpe,  g_kpe);
    cudaGetSymbolAddress((void**)&kv,   g_kv);
    cudaGetSymbolAddress((void**)&attn, g_attn);

    uint32_t *hidh, *hidl, *qanh, *qanl, *ckvnh, *ckvnl, *attnh, *attnl;
    uint32_t *Wqath, *Wqatl, *Wkvath, *Wkvatl, *Wqbth, *Wqbtl, *Wkvbth, *Wkvbtl, *Woth, *Wotl;
    cudaGetSymbolAddress((void**)&hidh,  g_hidh);
    cudaGetSymbolAddress((void**)&hidl,  g_hidl);
    cudaGetSymbolAddress((void**)&qanh,  g_qanh);
    cudaGetSymbolAddress((void**)&qanl,  g_qanl);
    cudaGetSymbolAddress((void**)&ckvnh, g_ckvnh);
    cudaGetSymbolAddress((void**)&ckvnl, g_ckvnl);
    cudaGetSymbolAddress((void**)&attnh, g_attnh);
    cudaGetSymbolAddress((void**)&attnl, g_attnl);
    cudaGetSymbolAddress((void**)&Wqath, g_Wqath);
    cudaGetSymbolAddress((void**)&Wqatl, g_Wqatl);
    cudaGetSymbolAddress((void**)&Wkvath, g_Wkvath);
    cudaGetSymbolAddress((void**)&Wkvatl, g_Wkvatl);
    cudaGetSymbolAddress((void**)&Wqbth, g_Wqbth);
    cudaGetSymbolAddress((void**)&Wqbtl, g_Wqbtl);
    cudaGetSymbolAddress((void**)&Wkvbth, g_Wkvbth);
    cudaGetSymbolAddress((void**)&Wkvbtl, g_Wkvbtl);
    cudaGetSymbolAddress((void**)&Woth, g_Woth);
    cudaGetSymbolAddress((void**)&Wotl, g_Wotl);

    cudaFuncSetAttribute(gemm_bf16x3_kernel,
                         cudaFuncAttributeMaxDynamicSharedMemorySize, GEMM_SMEM_BYTES);

    dim3 wtb(32, 8);
    // weight transpose + split
    wt_split_kernel<<<dim3(1536 / 32, HID / 32),  wtb>>>(Wqath,  Wqatl,  Wqa,  HID,  QLR);
    wt_split_kernel<<<dim3( 640 / 32, HID / 32),  wtb>>>(Wkvath, Wkvatl, Wkva, HID,  CKVD);
    wt_split_kernel<<<dim3(3072 / 32, QLR / 32),  wtb>>>(Wqbth,  Wqbtl,  Wqb,  QLR,  NH * QHD);
    wt_split_kernel<<<dim3(4096 / 32, KVLR / 32), wtb>>>(Wkvbth, Wkvbtl, Wkvb, KVLR, NH * (NOPE + VD));
    wt_split_kernel<<<dim3(2048 / 32, (NH*VD) / 32), wtb>>>(Woth, Wotl, Wo, NH * VD, HID);
    // hidden split
    split_pack_kernel<<<(S_LEN * (HID/2) + 255) / 256, 256>>>(hidh, hidl, hidden, S_LEN * (HID/2));

    // 1) q_a = hidden @ Wqa   [2048 x 1536]
    gemm_bf16x3_kernel<<<dim3(1536 / 128, S_LEN / 128), 256, GEMM_SMEM_BYTES>>>(
        qa, hidh, hidl, Wqath, Wqatl, S_LEN, QLR, HID, QLR);
    // 2) ckv = hidden @ Wkva  [2048 x 576]
    gemm_bf16x3_kernel<<<dim3(640 / 128, S_LEN / 128), 256, GEMM_SMEM_BYTES>>>(
        ckv, hidh, hidl, Wkvath, Wkvatl, S_LEN, CKVD, HID, CKVD);
    // 3) rmsnorm(q_a) -> packed
    rmsnorm_pack_kernel<<<S_LEN, 256>>>(qanh, qanl, qa, qa_ln, QLR, QLR);
    // 4) rmsnorm(c_kv) -> packed
    rmsnorm_pack_kernel<<<S_LEN, 256>>>(ckvnh, ckvnl, ckv, kv_ln, KVLR, CKVD);
    // 5) q = q_a_n @ Wqb      [2048 x 3072]
    gemm_bf16x3_kernel<<<dim3(3072 / 128, S_LEN / 128), 256, GEMM_SMEM_BYTES>>>(
        q, qanh, qanl, Wqbth, Wqbtl, S_LEN, NH * QHD, QLR, NH * QHD);
    // 6) kv = ckv_n @ Wkvb    [2048 x 4096]
    gemm_bf16x3_kernel<<<dim3(4096 / 128, S_LEN / 128), 256, GEMM_SMEM_BYTES>>>(
        kv, ckvnh, ckvnl, Wkvbth, Wkvbtl, S_LEN, NH * 256, KVLR, NH * 256);
    // 7) RoPE
    rope_kernel<<<S_LEN, (NH + 1) * 32>>>(q, kpe, ckv, pos);
    // 8) flash attention
    size_t fa_smem = (size_t)FA_SMEM_FLOATS * sizeof(float);
    cudaFuncSetAttribute(flash_kernel,
                         cudaFuncAttributeMaxDynamicSharedMemorySize, (int)fa_smem);
    flash_kernel<<<dim3(S_LEN / FA_BM, NH), 256, fa_smem>>>(attn, q, kv, kpe);
    // split attn
    split_pack_kernel<<<(S_LEN * (NH*VD/2) + 255) / 256, 256>>>(attnh, attnl, attn, S_LEN * (NH*VD/2));
    // 9) out = attn @ Wo      [2048 x 2048]
    gemm_bf16x3_kernel<<<dim3(HID / 128, S_LEN / 128), 256, GEMM_SMEM_BYTES>>>(
        out, attnh, attnl, Woth, Wotl, S_LEN, HID, NH * VD, HID);
}

// round 8
// speedup vs baseline: 3.4814x; 2.1317x over previous
#include <cuda_runtime.h>
#include <cuda_bf16.h>
#include <math.h>
#include <stdint.h>

// ---------------------------------------------------------------------------
// Problem constants (DeepseekV3 MLA prefill, B=1, S=2048)
// ---------------------------------------------------------------------------
#define S_LEN  2048
#define HID    2048
#define NH     16
#define NOPE   128
#define ROPE_D 64
#define QHD    192
#define VD     128
#define QLR    1536
#define KVLR   512
#define CKVD   576

// ---------------------------------------------------------------------------
// Scratch (static __device__ arrays — no runtime allocation)
// ---------------------------------------------------------------------------
__device__ float g_qa  [S_LEN * QLR];
__device__ float g_q   [S_LEN * NH * QHD];
__device__ float g_ckv [S_LEN * CKVD];
__device__ float g_kpe [S_LEN * ROPE_D];
__device__ float g_kv  [S_LEN * NH * (NOPE + VD)];
__device__ float g_attn[S_LEN * NH * VD];

// Packed bf16 hi/lo activations (u32 = two K-adjacent bf16, lo16 = even k)
__device__ uint32_t g_hidh [S_LEN * (HID/2)];
__device__ uint32_t g_hidl [S_LEN * (HID/2)];
__device__ uint32_t g_qanh [S_LEN * (QLR/2)];
__device__ uint32_t g_qanl [S_LEN * (QLR/2)];
__device__ uint32_t g_ckvnh[S_LEN * (KVLR/2)];
__device__ uint32_t g_ckvnl[S_LEN * (KVLR/2)];
__device__ uint32_t g_attnh[S_LEN * (NH*VD/2)];
__device__ uint32_t g_attnl[S_LEN * (NH*VD/2)];

// Transposed + split weights: [Npad][K/2] words
__device__ uint32_t g_Wqath [1536 * (HID/2)];
__device__ uint32_t g_Wqatl [1536 * (HID/2)];
__device__ uint32_t g_Wkvath[ 640 * (HID/2)];
__device__ uint32_t g_Wkvatl[ 640 * (HID/2)];
__device__ uint32_t g_Wqbth [3072 * (QLR/2)];
__device__ uint32_t g_Wqbtl [3072 * (QLR/2)];
__device__ uint32_t g_Wkvbth[4096 * (KVLR/2)];
__device__ uint32_t g_Wkvbtl[4096 * (KVLR/2)];
__device__ uint32_t g_Woth  [2048 * (NH*VD/2)];
__device__ uint32_t g_Wotl  [2048 * (NH*VD/2)];

// Packed per-head flash inputs
__device__ uint32_t g_qph[NH * S_LEN * 96];      // Q  [h][s][96w]  (192 dims)
__device__ uint32_t g_qpl[NH * S_LEN * 96];
__device__ uint32_t g_kph[NH * S_LEN * 96];      // K  [h][s][96w]  (nope|rope)
__device__ uint32_t g_kpl[NH * S_LEN * 96];
__device__ uint32_t g_vth[NH * VD * (S_LEN/2)];  // V^T [h][vd][1024w]
__device__ uint32_t g_vtl[NH * VD * (S_LEN/2)];

// ---------------------------------------------------------------------------
// bf16 hi/lo split helpers
// ---------------------------------------------------------------------------
__device__ __forceinline__ void split2(float a, float b, uint32_t& hi, uint32_t& lo) {
    __nv_bfloat16 ah = __float2bfloat16(a);
    __nv_bfloat16 bh = __float2bfloat16(b);
    __nv_bfloat16 al = __float2bfloat16(a - __bfloat162float(ah));
    __nv_bfloat16 bl = __float2bfloat16(b - __bfloat162float(bh));
    hi = (uint32_t)__bfloat16_as_ushort(ah) | ((uint32_t)__bfloat16_as_ushort(bh) << 16);
    lo = (uint32_t)__bfloat16_as_ushort(al) | ((uint32_t)__bfloat16_as_ushort(bl) << 16);
}

__device__ __forceinline__ void mma_bf16(float c[4], const uint32_t a[4],
                                         const uint32_t b[2]) {
    asm volatile(
        "mma.sync.aligned.m16n8k16.row.col.f32.bf16.bf16.f32 "
        "{%0,%1,%2,%3}, {%4,%5,%6,%7}, {%8,%9}, {%0,%1,%2,%3};"
        : "+f"(c[0]), "+f"(c[1]), "+f"(c[2]), "+f"(c[3])
        : "r"(a[0]), "r"(a[1]), "r"(a[2]), "r"(a[3]), "r"(b[0]), "r"(b[1]));
}

#define CP16(dst, src) \
    asm volatile("cp.async.cg.shared.global [%0], [%1], 16;" :: "r"(dst), "l"(src))
#define CP_COMMIT() asm volatile("cp.async.commit_group;")

// ---------------------------------------------------------------------------
// Weight transpose + split
// ---------------------------------------------------------------------------
__global__ void __launch_bounds__(256) wt_split_kernel(
    uint32_t* __restrict__ Th, uint32_t* __restrict__ Tl,
    const float* __restrict__ W, int K, int N)
{
    __shared__ float t[32][33];
    const int n0 = blockIdx.x * 32;
    const int k0 = blockIdx.y * 32;
    const int tx = threadIdx.x, ty = threadIdx.y;
    const int n = n0 + tx;
#pragma unroll
    for (int i = 0; i < 4; i++) {
        int k = ty + i * 8;
        t[k][tx] = (n < N) ? W[(size_t)(k0 + k) * N + n] : 0.f;
    }
    __syncthreads();
    const int Kw = K >> 1;
#pragma unroll
    for (int it = 0; it < 2; it++) {
        int s  = ty * 32 + tx + it * 256;
        int nl = s >> 4, wd = s & 15;
        uint32_t hi, lo;
        split2(t[2 * wd][nl], t[2 * wd + 1][nl], hi, lo);
        size_t o = (size_t)(n0 + nl) * Kw + (k0 >> 1) + wd;
        Th[o] = hi;
        Tl[o] = lo;
    }
}

// ---------------------------------------------------------------------------
// Activation split
// ---------------------------------------------------------------------------
__global__ void split_pack_kernel(uint32_t* __restrict__ oh, uint32_t* __restrict__ ol,
                                  const float* __restrict__ x, int nWords)
{
    int i = blockIdx.x * 256 + threadIdx.x;
    if (i < nWords) {
        float2 v = ((const float2*)x)[i];
        uint32_t hi, lo;
        split2(v.x, v.y, hi, lo);
        oh[i] = hi;
        ol[i] = lo;
    }
}

// ---------------------------------------------------------------------------
// RMSNorm fused with hi/lo pack
// ---------------------------------------------------------------------------
__global__ void __launch_bounds__(256) rmsnorm_pack_kernel(
    uint32_t* __restrict__ oh, uint32_t* __restrict__ ol,
    const float* __restrict__ in, const float* __restrict__ w, int D, int ldin)
{
    const int row = blockIdx.x;
    const float* x = in + (size_t)row * ldin;

    float s = 0.f;
    for (int i = threadIdx.x; i < D; i += 256) {
        float v = x[i];
        s += v * v;
    }
#pragma unroll
    for (int o = 16; o; o >>= 1) s += __shfl_xor_sync(0xffffffffu, s, o);
    __shared__ float red[8];
    __shared__ float inv_s;
    if ((threadIdx.x & 31) == 0) red[threadIdx.x >> 5] = s;
    __syncthreads();
    if (threadIdx.x == 0) {
        float tt = 0.f;
#pragma unroll
        for (int i = 0; i < 8; i++) tt += red[i];
        inv_s = rsqrtf(tt / (float)D + 1e-6f);
    }
    __syncthreads();
    const float inv = inv_s;
    const int Dw = D >> 1;
    for (int i = threadIdx.x; i < Dw; i += 256) {
        float a = w[2 * i]     * (x[2 * i]     * inv);
        float b = w[2 * i + 1] * (x[2 * i + 1] * inv);
        uint32_t hi, lo;
        split2(a, b, hi, lo);
        oh[(size_t)row * Dw + i] = hi;
        ol[(size_t)row * Dw + i] = lo;
    }
}

// ---------------------------------------------------------------------------
// 3-term bf16 tensor GEMM (unchanged from R7)
// ---------------------------------------------------------------------------
#define GS_STAGE_WORDS 10240
#define GEMM_SMEM_BYTES (2 * GS_STAGE_WORDS * 4)

__global__ void __launch_bounds__(256, 2) gemm_bf16x3_kernel(
    float* __restrict__ C,
    const uint32_t* __restrict__ Ah, const uint32_t* __restrict__ Al,
    const uint32_t* __restrict__ Bh, const uint32_t* __restrict__ Bl,
    int M, int N, int K, int ldc)
{
    extern __shared__ uint32_t sw[];
    const int Kw  = K >> 1;
    const int tid = threadIdx.x;
    const int lane = tid & 31;
    const int w   = tid >> 5;
    const int wm  = w >> 2;
    const int wn  = w & 3;
    const int g   = lane >> 2;
    const int t   = lane & 3;
    const int m0  = blockIdx.y * 128;
    const int n0  = blockIdx.x * 128;
    const uint32_t sbase = (uint32_t)__cvta_generic_to_shared(sw);

    const int r0 = tid >> 2,          c0 = (tid & 3) * 4;
    const int r1 = (tid + 256) >> 2,  c1 = ((tid + 256) & 3) * 4;

    float acc[4][4][4];
#pragma unroll
    for (int mi = 0; mi < 4; mi++)
#pragma unroll
        for (int ni = 0; ni < 4; ni++)
#pragma unroll
            for (int e = 0; e < 4; e++) acc[mi][ni][e] = 0.f;

    const int nchunks = K / 32;

#define LOAD_CHUNK(ch, stage)                                                    \
    do {                                                                         \
        const int kw0 = (ch) * 16;                                               \
        uint32_t sb = sbase + (stage) * (GS_STAGE_WORDS * 4);                    \
        uint32_t dA0 = sb + (r0 * 20 + c0) * 4;                                  \
        uint32_t dA1 = sb + (r1 * 20 + c1) * 4;                                  \
        uint32_t dB0 = sb + (5120 + r0 * 20 + c0) * 4;                           \
        uint32_t dB1 = sb + (5120 + r1 * 20 + c1) * 4;                           \
        CP16(dA0,          Ah + (size_t)(m0 + r0) * Kw + kw0 + c0);              \
        CP16(dA1,          Ah + (size_t)(m0 + r1) * Kw + kw0 + c1);              \
        CP16(dA0 + 10240,  Al + (size_t)(m0 + r0) * Kw + kw0 + c0);              \
        CP16(dA1 + 10240,  Al + (size_t)(m0 + r1) * Kw + kw0 + c1);              \
        CP16(dB0,          Bh + (size_t)(n0 + r0) * Kw + kw0 + c0);              \
        CP16(dB1,          Bh + (size_t)(n0 + r1) * Kw + kw0 + c1);              \
        CP16(dB0 + 10240,  Bl + (size_t)(n0 + r0) * Kw + kw0 + c0);              \
        CP16(dB1 + 10240,  Bl + (size_t)(n0 + r1) * Kw + kw0 + c1);              \
    } while (0)

    LOAD_CHUNK(0, 0);
    CP_COMMIT();

    for (int ch = 0; ch < nchunks; ch++) {
        if (ch + 1 < nchunks) {
            LOAD_CHUNK(ch + 1, (ch + 1) & 1);
            CP_COMMIT();
            asm volatile("cp.async.wait_group 1;");
        } else {
            asm volatile("cp.async.wait_group 0;");
        }
        __syncthreads();

        const uint32_t* st  = sw + (ch & 1) * GS_STAGE_WORDS;
        const uint32_t* sAh = st;
        const uint32_t* sAl = st + 2560;
        const uint32_t* sBh = st + 5120;
        const uint32_t* sBl = st + 7680;

#pragma unroll
        for (int kk = 0; kk < 2; kk++) {
            const int off = kk * 8;
            uint32_t bh[4][2], bl[4][2];
#pragma unroll
            for (int ni = 0; ni < 4; ni++) {
                int ba = (wn * 32 + ni * 8 + g) * 20 + off + t;
                bh[ni][0] = sBh[ba];
                bh[ni][1] = sBh[ba + 4];
                bl[ni][0] = sBl[ba];
                bl[ni][1] = sBl[ba + 4];
            }
#pragma unroll
            for (int mi = 0; mi < 4; mi++) {
                int aa = (wm * 64 + mi * 16 + g) * 20 + off + t;
                uint32_t ah[4], al[4];
                ah[0] = sAh[aa];       ah[1] = sAh[aa + 160];
                ah[2] = sAh[aa + 4];   ah[3] = sAh[aa + 164];
                al[0] = sAl[aa];       al[1] = sAl[aa + 160];
                al[2] = sAl[aa + 4];   al[3] = sAl[aa + 164];
#pragma unroll
                for (int ni = 0; ni < 4; ni++) {
                    mma_bf16(acc[mi][ni], ah, bh[ni]);
                    mma_bf16(acc[mi][ni], al, bh[ni]);
                    mma_bf16(acc[mi][ni], ah, bl[ni]);
                }
            }
        }
        __syncthreads();
    }
#undef LOAD_CHUNK

#pragma unroll
    for (int mi = 0; mi < 4; mi++) {
        int rr0 = m0 + wm * 64 + mi * 16 + g;
        int rr1 = rr0 + 8;
#pragma unroll
        for (int ni = 0; ni < 4; ni++) {
            int c = n0 + wn * 32 + ni * 8 + 2 * t;
            if (c < N) {
                *(float2*)(C + (size_t)rr0 * ldc + c) =
                    make_float2(acc[mi][ni][0], acc[mi][ni][1]);
                *(float2*)(C + (size_t)rr1 * ldc + c) =
                    make_float2(acc[mi][ni][2], acc[mi][ni][3]);
            }
        }
    }
}

// ---------------------------------------------------------------------------
// RoPE (deinterleave + rotate_half fused)
// ---------------------------------------------------------------------------
__global__ void rope_kernel(float* __restrict__ q, float* __restrict__ kpe,
                            const float* __restrict__ ckv,
                            const int* __restrict__ pos_ids)
{
    const int srow = blockIdx.x;
    const int tid  = threadIdx.x;
    const int j    = tid & 31;

    const float pos  = (float)pos_ids[srow];
    const float freq = __expf(-((2.f * (float)j) / 64.f) * logf(10000.f));
    const float ang  = pos * freq;
    float cv, sv;
    __sincosf(ang, &sv, &cv);

    if (tid < NH * 32) {
        const int h = tid >> 5;
        float* base = q + (size_t)srow * (NH * QHD) + h * QHD + NOPE;
        float x0 = base[2 * j];
        float x1 = base[2 * j + 1];
        __syncwarp();
        base[j]      = x0 * cv - x1 * sv;
        base[32 + j] = x1 * cv + x0 * sv;
    } else {
        const float* src = ckv + (size_t)srow * CKVD + KVLR;
        float x0 = src[2 * j];
        float x1 = src[2 * j + 1];
        float* dst = kpe + (size_t)srow * ROPE_D;
        dst[j]      = x0 * cv - x1 * sv;
        dst[32 + j] = x1 * cv + x0 * sv;
    }
}

// ---------------------------------------------------------------------------
// Pack Q and K per head into hi/lo word arrays [h][s][96w]
//   Q: from g_q [s][h*192 + d]
//   K: dims 0..127 from g_kv [s][h*256 + d]; dims 128..191 from g_kpe [s][..]
// ---------------------------------------------------------------------------
__global__ void qk_pack_kernel(
    uint32_t* __restrict__ qh, uint32_t* __restrict__ ql,
    uint32_t* __restrict__ kh, uint32_t* __restrict__ kl,
    const float* __restrict__ q, const float* __restrict__ kv,
    const float* __restrict__ kpe)
{
    int idx = blockIdx.x * 256 + threadIdx.x;   // NH*S*96 total
    if (idx >= NH * S_LEN * 96) return;
    int w = idx % 96;
    int s = (idx / 96) % S_LEN;
    int h = idx / (96 * S_LEN);

    uint32_t hi, lo;
    // Q
    const float* qp = q + (size_t)s * (NH * QHD) + h * QHD + 2 * w;
    split2(qp[0], qp[1], hi, lo);
    qh[idx] = hi; ql[idx] = lo;
    // K
    float a, b;
    if (w < 64) {
        const float* kp = kv + (size_t)s * (NH * 256) + h * 256 + 2 * w;
        a = kp[0]; b = kp[1];
    } else {
        const float* kp = kpe + (size_t)s * ROPE_D + 2 * (w - 64);
        a = kp[0]; b = kp[1];
    }
    split2(a, b, hi, lo);
    kh[idx] = hi; kl[idx] = lo;
}

// ---------------------------------------------------------------------------
// Pack V transposed: g_kv [s][h*256+128+vd] -> vt [h][vd][s/2 words]
// grid (S/64, VD/32, NH), block 256
// ---------------------------------------------------------------------------
__global__ void vt_pack_kernel(uint32_t* __restrict__ vth, uint32_t* __restrict__ vtl,
                               const float* __restrict__ kv)
{
    __shared__ float tile[64][33];
    const int s0 = blockIdx.x * 64, v0 = blockIdx.y * 32, h = blockIdx.z;
    const int tid = threadIdx.x;
#pragma unroll
    for (int i = 0; i < 8; i++) {
        int e = tid + i * 256;
        int s = e >> 5, vd = e & 31;
        tile[s][vd] = kv[(size_t)(s0 + s) * (NH * 256) + h * 256 + NOPE + v0 + vd];
    }
    __syncthreads();
#pragma unroll
    for (int i = 0; i < 4; i++) {
        int e = tid + i * 256;
        int vd = e >> 5, sw_ = e & 31;
        uint32_t hi, lo;
        split2(tile[2 * sw_][vd], tile[2 * sw_ + 1][vd], hi, lo);
        size_t o = (size_t)(h * VD + v0 + vd) * (S_LEN / 2) + (s0 >> 1) + sw_;
        vth[o] = hi; vtl[o] = lo;
    }
}

// ---------------------------------------------------------------------------
// Tensor-core causal flash attention (3-term bf16, fp32 softmax/acc).
//   BM=BN=64, D=192 (12 k16 atoms), DV=128. 256 threads, 8 warps.
//   Warp grid 4m x 2n: scores 16x32/warp, O 16x64/warp.
// smem words: sQ 2*6400, sK 2*2*6400, sVt 2*4608, sP 2*2304, stats 256
//           = 52480 words = 209920 B
// ---------------------------------------------------------------------------
#define FLASH_SMEM_BYTES (52480 * 4)

__global__ void __launch_bounds__(256, 1) flash_mma_kernel(
    float* __restrict__ O,
    const uint32_t* __restrict__ Qh, const uint32_t* __restrict__ Ql,
    const uint32_t* __restrict__ Kh, const uint32_t* __restrict__ Kl,
    const uint32_t* __restrict__ Vh, const uint32_t* __restrict__ Vl)
{
    extern __shared__ uint32_t sw[];
    uint32_t* sQh = sw;                // 64 x 100
    uint32_t* sQl = sw + 6400;
    uint32_t* sKh = sw + 12800;        // 2 bufs x 64 x 100
    uint32_t* sKl = sw + 25600;
    uint32_t* sVh = sw + 38400;        // 128 x 36
    uint32_t* sVl = sw + 43008;
    uint32_t* sPh = sw + 47616;        // 64 x 36
    uint32_t* sPl = sw + 49920;
    float*    sMax = (float*)(sw + 52224);  // [64][2]
    float*    sSum = sMax + 128;            // [64][2]

    const int tid  = threadIdx.x;
    const int lane = tid & 31;
    const int w    = tid >> 5;
    const int wm   = w & 3;
    const int wn   = w >> 2;
    const int g    = lane >> 2;
    const int t    = lane & 3;
    const int h    = blockIdx.y;
    const int qb   = blockIdx.x;
    const int q0   = qb * 64;
    const uint32_t sb = (uint32_t)__cvta_generic_to_shared(sw);

    const uint32_t* Qhp = Qh + ((size_t)h * S_LEN + q0) * 96;
    const uint32_t* Qlp = Ql + ((size_t)h * S_LEN + q0) * 96;
    const uint32_t* Khp = Kh + (size_t)h * S_LEN * 96;
    const uint32_t* Klp = Kl + (size_t)h * S_LEN * 96;
    const uint32_t* Vhp = Vh + (size_t)h * VD * (S_LEN / 2);
    const uint32_t* Vlp = Vl + (size_t)h * VD * (S_LEN / 2);

    // ---- cp Q + K0 (group 0) ----
#pragma unroll
    for (int i = 0; i < 6; i++) {
        int c = tid + i * 256;
        int r = c / 24, c4 = (c % 24) * 4;
        CP16(sb + (r * 100 + c4) * 4,           Qhp + r * 96 + c4);
        CP16(sb + (6400 + r * 100 + c4) * 4,    Qlp + r * 96 + c4);
        CP16(sb + (12800 + r * 100 + c4) * 4,   Khp + r * 96 + c4);
        CP16(sb + (25600 + r * 100 + c4) * 4,   Klp + r * 96 + c4);
    }
    CP_COMMIT();

    float oacc[8][4];
#pragma unroll
    for (int ni = 0; ni < 8; ni++)
#pragma unroll
        for (int e = 0; e < 4; e++) oacc[ni][e] = 0.f;
    float mi0 = -1e30f, mi1 = -1e30f, li0 = 0.f, li1 = 0.f;

    const int r0 = wm * 16 + g, r1 = r0 + 8;
    const int qi0 = q0 + r0, qi1 = q0 + r1;
    const float scale = rsqrtf((float)QHD);

    for (int kb = 0; kb <= qb; kb++) {
        const int k0 = kb * 64;
        // issue V(kb)
#pragma unroll
        for (int i = 0; i < 4; i++) {
            int c = tid + i * 256;
            int r = c >> 3, c4 = (c & 7) * 4;
            CP16(sb + (38400 + r * 36 + c4) * 4, Vhp + (size_t)r * (S_LEN/2) + (k0 >> 1) + c4);
            CP16(sb + (43008 + r * 36 + c4) * 4, Vlp + (size_t)r * (S_LEN/2) + (k0 >> 1) + c4);
        }
        CP_COMMIT();
        // prefetch K(kb+1)
        if (kb < qb) {
            const int kn = (kb + 1) * 64;
            const int bo = ((kb + 1) & 1) * 6400;
#pragma unroll
            for (int i = 0; i < 6; i++) {
                int c = tid + i * 256;
                int r = c / 24, c4 = (c % 24) * 4;
                CP16(sb + (12800 + bo + r * 100 + c4) * 4, Khp + (size_t)(kn + r) * 96 + c4);
                CP16(sb + (25600 + bo + r * 100 + c4) * 4, Klp + (size_t)(kn + r) * 96 + c4);
            }
            CP_COMMIT();
            asm volatile("cp.async.wait_group 2;");   // K(kb) (and Q) ready
        } else {
            asm volatile("cp.async.wait_group 1;");
        }
        __syncthreads();

        // ---- QK^T : 12 k-atoms ----
        const uint32_t* kbh = sKh + (kb & 1) * 6400;
        const uint32_t* kbl = sKl + (kb & 1) * 6400;
        float sacc[4][4];
#pragma unroll
        for (int ni = 0; ni < 4; ni++)
#pragma unroll
            for (int e = 0; e < 4; e++) sacc[ni][e] = 0.f;

#pragma unroll
        for (int ka = 0; ka < 12; ka++) {
            uint32_t bh[4][2], bl[4][2];
#pragma unroll
            for (int ni = 0; ni < 4; ni++) {
                int ba = (wn * 32 + ni * 8 + g) * 100 + ka * 8 + t;
                bh[ni][0] = kbh[ba]; bh[ni][1] = kbh[ba + 4];
                bl[ni][0] = kbl[ba]; bl[ni][1] = kbl[ba + 4];
            }
            int aa = r0 * 100 + ka * 8 + t;
            uint32_t ah[4], al[4];
            ah[0] = sQh[aa]; ah[1] = sQh[aa + 800]; ah[2] = sQh[aa + 4]; ah[3] = sQh[aa + 804];
            al[0] = sQl[aa]; al[1] = sQl[aa + 800]; al[2] = sQl[aa + 4]; al[3] = sQl[aa + 804];
#pragma unroll
            for (int ni = 0; ni < 4; ni++) {
                mma_bf16(sacc[ni], ah, bh[ni]);
                mma_bf16(sacc[ni], al, bh[ni]);
                mma_bf16(sacc[ni], ah, bl[ni]);
            }
        }

        // ---- softmax ----
        const bool diag = (kb == qb);
        float v0[8], v1[8];
        float rm0 = -1e30f, rm1 = -1e30f;
#pragma unroll
        for (int ni = 0; ni < 4; ni++) {
#pragma unroll
            for (int e = 0; e < 2; e++) {
                int col = k0 + wn * 32 + ni * 8 + 2 * t + e;
                float x0 = sacc[ni][e]     * scale;
                float x1 = sacc[ni][2 + e] * scale;
                if (diag && col > qi0) x0 = -1e30f;
                if (diag && col > qi1) x1 = -1e30f;
                v0[ni * 2 + e] = x0;
                v1[ni * 2 + e] = x1;
                rm0 = fmaxf(rm0, x0);
                rm1 = fmaxf(rm1, x1);
            }
        }
        rm0 = fmaxf(rm0, __shfl_xor_sync(0xffffffffu, rm0, 1));
        rm0 = fmaxf(rm0, __shfl_xor_sync(0xffffffffu, rm0, 2));
        rm1 = fmaxf(rm1, __shfl_xor_sync(0xffffffffu, rm1, 1));
        rm1 = fmaxf(rm1, __shfl_xor_sync(0xffffffffu, rm1, 2));
        if (t == 0) {
            sMax[r0 * 2 + wn] = rm0;
            sMax[r1 * 2 + wn] = rm1;
        }
        __syncthreads();
        float mn0 = fmaxf(mi0, fmaxf(sMax[r0 * 2], sMax[r0 * 2 + 1]));
        float mn1 = fmaxf(mi1, fmaxf(sMax[r1 * 2], sMax[r1 * 2 + 1]));
        float al0 = __expf(mi0 - mn0);
        float al1 = __expf(mi1 - mn1);
        float ls0 = 0.f, ls1 = 0.f;
#pragma unroll
        for (int i = 0; i < 8; i++) {
            v0[i] = __expf(v0[i] - mn0); ls0 += v0[i];
            v1[i] = __expf(v1[i] - mn1); ls1 += v1[i];
        }
        // pack P
#pragma unroll
        for (int ni = 0; ni < 4; ni++) {
            uint32_t hi, lo;
            split2(v0[ni * 2], v0[ni * 2 + 1], hi, lo);
            sPh[r0 * 36 + wn * 16 + ni * 4 + t] = hi;
            sPl[r0 * 36 + wn * 16 + ni * 4 + t] = lo;
            split2(v1[ni * 2], v1[ni * 2 + 1], hi, lo);
            sPh[r1 * 36 + wn * 16 + ni * 4 + t] = hi;
            sPl[r1 * 36 + wn * 16 + ni * 4 + t] = lo;
        }
        ls0 += __shfl_xor_sync(0xffffffffu, ls0, 1);
        ls0 += __shfl_xor_sync(0xffffffffu, ls0, 2);
        ls1 += __shfl_xor_sync(0xffffffffu, ls1, 1);
        ls1 += __shfl_xor_sync(0xffffffffu, ls1, 2);
        if (t == 0) {
            sSum[r0 * 2 + wn] = ls0;
            sSum[r1 * 2 + wn] = ls1;
        }
        __syncthreads();
        li0 = li0 * al0 + sSum[r0 * 2] + sSum[r0 * 2 + 1];
        li1 = li1 * al1 + sSum[r1 * 2] + sSum[r1 * 2 + 1];
        mi0 = mn0; mi1 = mn1;
#pragma unroll
        for (int ni = 0; ni < 8; ni++) {
            oacc[ni][0] *= al0; oacc[ni][1] *= al0;
            oacc[ni][2] *= al1; oacc[ni][3] *= al1;
        }
        // wait for V(kb)
        if (kb < qb) asm volatile("cp.async.wait_group 1;");
        else         asm volatile("cp.async.wait_group 0;");
        __syncthreads();

        // ---- PV : 4 k-atoms, 8 n-atoms (vd) ----
#pragma unroll
        for (int ka = 0; ka < 4; ka++) {
            int aa = r0 * 36 + ka * 8 + t;
            uint32_t ah[4], al[4];
            ah[0] = sPh[aa]; ah[1] = sPh[aa + 288]; ah[2] = sPh[aa + 4]; ah[3] = sPh[aa + 292];
            al[0] = sPl[aa]; al[1] = sPl[aa + 288]; al[2] = sPl[aa + 4]; al[3] = sPl[aa + 292];
#pragma unroll
            for (int ni = 0; ni < 8; ni++) {
                int ba = (wn * 64 + ni * 8 + g) * 36 + ka * 8 + t;
                uint32_t bh[2], bl[2];
                bh[0] = sVh[ba]; bh[1] = sVh[ba + 4];
                bl[0] = sVl[ba]; bl[1] = sVl[ba + 4];
                mma_bf16(oacc[ni], ah, bh);
                mma_bf16(oacc[ni], al, bh);
                mma_bf16(oacc[ni], ah, bl);
            }
        }
        __syncthreads();   // protect sV / sP reuse next tile
    }

    // ---- epilogue ----
    float inv0 = 1.f / li0, inv1 = 1.f / li1;
#pragma unroll
    for (int ni = 0; ni < 8; ni++) {
        int col = h * VD + wn * 64 + ni * 8 + 2 * t;
        *(float2*)(O + (size_t)(q0 + r0) * (NH * VD) + col) =
            make_float2(oacc[ni][0] * inv0, oacc[ni][1] * inv0);
        *(float2*)(O + (size_t)(q0 + r1) * (NH * VD) + col) =
            make_float2(oacc[ni][2] * inv1, oacc[ni][3] * inv1);
    }
}

// ---------------------------------------------------------------------------
// Launch
// ---------------------------------------------------------------------------
extern "C" void kernel_launch(void* const* d_in, const int* in_sizes, int n_in,
                              void* d_out, int out_size)
{
    const float* hidden = (const float*)d_in[0];
    const int*   pos    = (const int*)d_in[1];
    const float* Wqa    = (const float*)d_in[2];
    const float* qa_ln  = (const float*)d_in[3];
    const float* Wqb    = (const float*)d_in[4];
    const float* Wkva   = (const float*)d_in[5];
    const float* kv_ln  = (const float*)d_in[6];
    const float* Wkvb   = (const float*)d_in[7];
    const float* Wo     = (const float*)d_in[8];
    float* out = (float*)d_out;

    float *qa, *q, *ckv, *kpe, *kv, *attn;
    cudaGetSymbolAddress((void**)&qa,   g_qa);
    cudaGetSymbolAddress((void**)&q,    g_q);
    cudaGetSymbolAddress((void**)&ckv,  g_ckv);
    cudaGetSymbolAddress((void**)&kpe,  g_kpe);
    cudaGetSymbolAddress((void**)&kv,   g_kv);
    cudaGetSymbolAddress((void**)&attn, g_attn);

    uint32_t *hidh, *hidl, *qanh, *qanl, *ckvnh, *ckvnl, *attnh, *attnl;
    uint32_t *Wqath, *Wqatl, *Wkvath, *Wkvatl, *Wqbth, *Wqbtl, *Wkvbth, *Wkvbtl, *Woth, *Wotl;
    uint32_t *qph, *qpl, *kph, *kpl, *vth, *vtl;
    cudaGetSymbolAddress((void**)&hidh,  g_hidh);
    cudaGetSymbolAddress((void**)&hidl,  g_hidl);
    cudaGetSymbolAddress((void**)&qanh,  g_qanh);
    cudaGetSymbolAddress((void**)&qanl,  g_qanl);
    cudaGetSymbolAddress((void**)&ckvnh, g_ckvnh);
    cudaGetSymbolAddress((void**)&ckvnl, g_ckvnl);
    cudaGetSymbolAddress((void**)&attnh, g_attnh);
    cudaGetSymbolAddress((void**)&attnl, g_attnl);
    cudaGetSymbolAddress((void**)&Wqath, g_Wqath);
    cudaGetSymbolAddress((void**)&Wqatl, g_Wqatl);
    cudaGetSymbolAddress((void**)&Wkvath, g_Wkvath);
    cudaGetSymbolAddress((void**)&Wkvatl, g_Wkvatl);
    cudaGetSymbolAddress((void**)&Wqbth, g_Wqbth);
    cudaGetSymbolAddress((void**)&Wqbtl, g_Wqbtl);
    cudaGetSymbolAddress((void**)&Wkvbth, g_Wkvbth);
    cudaGetSymbolAddress((void**)&Wkvbtl, g_Wkvbtl);
    cudaGetSymbolAddress((void**)&Woth, g_Woth);
    cudaGetSymbolAddress((void**)&Wotl, g_Wotl);
    cudaGetSymbolAddress((void**)&qph, g_qph);
    cudaGetSymbolAddress((void**)&qpl, g_qpl);
    cudaGetSymbolAddress((void**)&kph, g_kph);
    cudaGetSymbolAddress((void**)&kpl, g_kpl);
    cudaGetSymbolAddress((void**)&vth, g_vth);
    cudaGetSymbolAddress((void**)&vtl, g_vtl);

    cudaFuncSetAttribute(gemm_bf16x3_kernel,
                         cudaFuncAttributeMaxDynamicSharedMemorySize, GEMM_SMEM_BYTES);
    cudaFuncSetAttribute(flash_mma_kernel,
                         cudaFuncAttributeMaxDynamicSharedMemorySize, FLASH_SMEM_BYTES);

    dim3 wtb(32, 8);
    wt_split_kernel<<<dim3(1536 / 32, HID / 32),  wtb>>>(Wqath,  Wqatl,  Wqa,  HID,  QLR);
    wt_split_kernel<<<dim3( 640 / 32, HID / 32),  wtb>>>(Wkvath, Wkvatl, Wkva, HID,  CKVD);
    wt_split_kernel<<<dim3(3072 / 32, QLR / 32),  wtb>>>(Wqbth,  Wqbtl,  Wqb,  QLR,  NH * QHD);
    wt_split_kernel<<<dim3(4096 / 32, KVLR / 32), wtb>>>(Wkvbth, Wkvbtl, Wkvb, KVLR, NH * (NOPE + VD));
    wt_split_kernel<<<dim3(2048 / 32, (NH*VD) / 32), wtb>>>(Woth, Wotl, Wo, NH * VD, HID);
    split_pack_kernel<<<(S_LEN * (HID/2) + 255) / 256, 256>>>(hidh, hidl, hidden, S_LEN * (HID/2));

    // 1) q_a = hidden @ Wqa
    gemm_bf16x3_kernel<<<dim3(1536 / 128, S_LEN / 128), 256, GEMM_SMEM_BYTES>>>(
        qa, hidh, hidl, Wqath, Wqatl, S_LEN, QLR, HID, QLR);
    // 2) ckv = hidden @ Wkva
    gemm_bf16x3_kernel<<<dim3(640 / 128, S_LEN / 128), 256, GEMM_SMEM_BYTES>>>(
        ckv, hidh, hidl, Wkvath, Wkvatl, S_LEN, CKVD, HID, CKVD);
    // 3-4) rmsnorms -> packed
    rmsnorm_pack_kernel<<<S_LEN, 256>>>(qanh, qanl, qa, qa_ln, QLR, QLR);
    rmsnorm_pack_kernel<<<S_LEN, 256>>>(ckvnh, ckvnl, ckv, kv_ln, KVLR, CKVD);
    // 5) q = q_a_n @ Wqb
    gemm_bf16x3_kernel<<<dim3(3072 / 128, S_LEN / 128), 256, GEMM_SMEM_BYTES>>>(
        q, qanh, qanl, Wqbth, Wqbtl, S_LEN, NH * QHD, QLR, NH * QHD);
    // 6) kv = ckv_n @ Wkvb
    gemm_bf16x3_kernel<<<dim3(4096 / 128, S_LEN / 128), 256, GEMM_SMEM_BYTES>>>(
        kv, ckvnh, ckvnl, Wkvbth, Wkvbtl, S_LEN, NH * 256, KVLR, NH * 256);
    // 7) RoPE
    rope_kernel<<<S_LEN, (NH + 1) * 32>>>(q, kpe, ckv, pos);
    // 8) pack flash inputs
    qk_pack_kernel<<<(NH * S_LEN * 96 + 255) / 256, 256>>>(qph, qpl, kph, kpl, q, kv, kpe);
    vt_pack_kernel<<<dim3(S_LEN / 64, VD / 32, NH), 256>>>(vth, vtl, kv);
    // 9) tensor-core flash attention
    flash_mma_kernel<<<dim3(S_LEN / 64, NH), 256, FLASH_SMEM_BYTES>>>(
        attn, qph, qpl, kph, kpl, vth, vtl);
    // 10) split attn + out = attn @ Wo
    split_pack_kernel<<<(S_LEN * (NH*VD/2) + 255) / 256, 256>>>(attnh, attnl, attn, S_LEN * (NH*VD/2));
    gemm_bf16x3_kernel<<<dim3(HID / 128, S_LEN / 128), 256, GEMM_SMEM_BYTES>>>(
        out, attnh, attnl, Woth, Wotl, S_LEN, HID, NH * VD, HID);
}